// round 6
// baseline (speedup 1.0000x reference)
#include <cuda_runtime.h>
#include <cstdint>

// Problem constants
#define Tn   2048
#define Bn   64
#define Vn   4096
#define En   128
#define H2n  128
#define Sn   8

// Scratch (no allocations allowed)
__device__ float g_proj[2][Vn * 512];      // per-direction: proj[v][gate] = W_ih @ emb[v] + b  (16 MB, L2-resident)
__device__ float g_pooled[Bn * Sn * 256];  // pooled[b][s][h]  (512 KB)

// ---------------------------------------------------------------------------
// helpers
// ---------------------------------------------------------------------------
__device__ __forceinline__ unsigned long long ffma2(unsigned long long a,
                                                    unsigned long long b,
                                                    unsigned long long c) {
    unsigned long long d;
    asm("fma.rn.f32x2 %0, %1, %2, %3;" : "=l"(d) : "l"(a), "l"(b), "l"(c));
    return d;
}
__device__ __forceinline__ float2 unpack2(unsigned long long u) {
    float2 f;
    f.x = __uint_as_float((unsigned)(u & 0xffffffffull));
    f.y = __uint_as_float((unsigned)(u >> 32));
    return f;
}
__device__ __forceinline__ float sigm(float x) {
    return __fdividef(1.f, 1.f + __expf(-x));
}
__device__ __forceinline__ float tanh_fast(float x) {
    float e = __expf(2.f * x);                 // saturates correctly at +/-inf
    return 1.f - __fdividef(2.f, e + 1.f);
}

// ---------------------------------------------------------------------------
// Kernel A: proj[d][v][j] = dot(emb[v], W_ih_d[j]) + b_d[j]
// grid (4096, 2) x 512 threads
// ---------------------------------------------------------------------------
__global__ void proj_kernel(const float* __restrict__ emb,
                            const float* __restrict__ Wf, const float* __restrict__ bf,
                            const float* __restrict__ Wb, const float* __restrict__ bb) {
    __shared__ float x[En];
    int v = blockIdx.x, d = blockIdx.y, j = threadIdx.x;
    const float* W    = d ? Wb : Wf;
    const float* bias = d ? bb : bf;
    if (j < En) x[j] = emb[v * En + j];
    __syncthreads();
    const float4* wr = (const float4*)(W + j * En);
    float acc = 0.f;
#pragma unroll
    for (int e = 0; e < En / 4; e++) {
        float4 w = wr[e];
        acc += w.x * x[4 * e] + w.y * x[4 * e + 1] + w.z * x[4 * e + 2] + w.w * x[4 * e + 3];
    }
    g_proj[d][v * 512 + j] = acc + bias[j];
}

// ---------------------------------------------------------------------------
// Kernel B: recurrent biLSTM with fused ragged max-pool.
// grid 128 = (sample, direction); 256 threads, thread k owns gate rows k and k+256.
//   k <  128 : rows k (i-gate) and k+256 (g-gate)  -> p = sig(i)*tanh(g)
//   k >= 128 : rows k (f-gate) and k+256 (o-gate)  -> c,h update, pooling
// Weights: row k fully in regs (64 f32x2); row k+256: 32 f32x2 regs + 32 f32x2 smem.
// ---------------------------------------------------------------------------
#define NREGW  32
#define NSMEMW 32
#define LSTM_SMEM (NSMEMW * 256 * 8 + 128 * 4 + 128 * 4 + Sn * 128 * 4)  // 70656 B

extern "C" __global__ void __launch_bounds__(256, 1)
lstm_kernel(const int* __restrict__ sentence, const int* __restrict__ lens,
            const float* __restrict__ Whhf, const float* __restrict__ Whhb) {
    extern __shared__ unsigned long long dsm[];
    unsigned long long (*sW)[256] = (unsigned long long (*)[256])dsm;  // [32][256] slot-major
    float* h_s  = (float*)(dsm + NSMEMW * 256);   // 128 floats, 16B aligned
    float* pbuf = h_s + 128;                      // 128 floats
    float* wmax = pbuf + 128;                     // [8][128]

    int bid = blockIdx.x;
    int b = bid >> 1, d = bid & 1;
    int L = lens[b];
    int w = (L + 7) >> 3;          // per-sample pooling window
    int k = threadIdx.x;

    const float* W     = d ? Whhb : Whhf;
    const float* projd = g_proj[d];
    const int*   toks  = sentence + b * Tn;

    // --- load W_hh rows k and k+256 ---
    unsigned long long a[64], bw[NREGW];
    {
        const ulonglong2* pa = (const ulonglong2*)(W + k * En);
#pragma unroll
        for (int e = 0; e < 32; e++) {
            ulonglong2 t = pa[e];
            a[2 * e] = t.x; a[2 * e + 1] = t.y;
        }
        const unsigned long long* pb = (const unsigned long long*)(W + (k + 256) * En);
#pragma unroll
        for (int j = 0; j < NREGW; j++) bw[j] = pb[j];
#pragma unroll
        for (int j = 0; j < NSMEMW; j++) sW[j][k] = pb[NREGW + j];
    }
    if (k < 128) h_s[k] = 0.f;
    for (int i = k; i < Sn * 128; i += 256) wmax[i] = -3.402823e38f;
    __syncthreads();

    float c = 0.f;
    int segInit = (L - 1) / w; if (segInit > 7) segInit = 7;
    int seg   = d ? segInit : 0;
    int bndUp = w;
    int bndLo = seg * w;

    // prefetch first xg row
    int tok0 = toks[d ? (L - 1) : 0];
    float xga = __ldg(projd + tok0 * 512 + k);
    float xgb = __ldg(projd + tok0 * 512 + k + 256);

    for (int s = 0; s < L; s++) {
        int tt = d ? (L - 1 - s) : s;

        // prefetch next step's input-gate row (hides L2 latency under the FMA loop)
        int s2   = (s + 1 < L) ? (s + 1) : s;
        int tt2  = d ? (L - 1 - s2) : s2;
        int tok2 = __ldg(toks + tt2);
        float nxa = __ldg(projd + tok2 * 512 + k);
        float nxb = __ldg(projd + tok2 * 512 + k + 256);

        // --- dot products: rows k and k+256 against h (f32x2 packed FMA) ---
        unsigned long long A0 = 0, A1 = 0, B0 = 0, B1 = 0;
        const ulonglong2* hv = (const ulonglong2*)h_s;
#pragma unroll
        for (int e = 0; e < 32; e++) {
            ulonglong2 hp = hv[e];   // broadcast LDS.128: h[4e..4e+3]
            A0 = ffma2(a[2 * e],     hp.x, A0);
            A1 = ffma2(a[2 * e + 1], hp.y, A1);
            unsigned long long w0 = (2 * e     < NREGW) ? bw[2 * e]     : sW[2 * e - NREGW][k];
            unsigned long long w1 = (2 * e + 1 < NREGW) ? bw[2 * e + 1] : sW[2 * e + 1 - NREGW][k];
            B0 = ffma2(w0, hp.x, B0);
            B1 = ffma2(w1, hp.y, B1);
        }
        float2 fA0 = unpack2(A0), fA1 = unpack2(A1);
        float2 fB0 = unpack2(B0), fB1 = unpack2(B1);
        float gA = (fA0.x + fA0.y) + (fA1.x + fA1.y) + xga;
        float gB = (fB0.x + fB0.y) + (fB1.x + fB1.y) + xgb;

        float sf = 0.f, so = 0.f;
        if (k < 128) {
            pbuf[k] = sigm(gA) * tanh_fast(gB);        // sig(i)*tanh(g)
        } else {
            sf = sigm(gA);                              // sig(f)
            so = sigm(gB);                              // sig(o)
        }
        __syncthreads();
        if (k >= 128) {
            int kk = k - 128;
            c = sf * c + pbuf[kk];
            float hn = so * tanh_fast(c);
            h_s[kk] = hn;
            float* wm = wmax + seg * 128 + kk;          // fused max-pool
            *wm = fmaxf(*wm, hn);
        }
        __syncthreads();

        // window-boundary tracking (uniform branch, no per-step division)
        if (d) { if (tt == bndLo && seg > 0) { seg--; bndLo -= w; } }
        else   { if (tt + 1 == bndUp && seg < 7) { seg++; bndUp += w; } }
        xga = nxa; xgb = nxb;
    }

    __syncthreads();
    // epilogue: only window 7 can overlap the zero pad (pad length < 8 <= w)
    bool pad7 = (8 * w > L);
    for (int i = k; i < Sn * 128; i += 256) {
        int s = i >> 7, kk = i & 127;
        float v = wmax[i];
        if (s == 7 && pad7) v = fmaxf(v, 0.f);
        g_pooled[(b * Sn + s) * 256 + d * 128 + kk] = v;
    }
}

// ---------------------------------------------------------------------------
// Kernel C: out[b][c] = b_dense[c] + sum_{s,h} pooled[b][s][h] * W_dense[c][h*8+s]
// ---------------------------------------------------------------------------
__global__ void dense_kernel(const float* __restrict__ Wd, const float* __restrict__ bd,
                             float* __restrict__ out) {
    int b = blockIdx.x, t = threadIdx.x;
    const float* p = g_pooled + b * 2048;
    float a0 = 0.f, a1 = 0.f;
    for (int i = t; i < 2048; i += 256) {
        int s = i >> 8, hh = i & 255;
        float v = p[i];
        a0 += v * Wd[hh * 8 + s];
        a1 += v * Wd[2048 + hh * 8 + s];
    }
#pragma unroll
    for (int o = 16; o > 0; o >>= 1) {
        a0 += __shfl_down_sync(0xffffffffu, a0, o);
        a1 += __shfl_down_sync(0xffffffffu, a1, o);
    }
    __shared__ float r0[8], r1[8];
    if ((t & 31) == 0) { r0[t >> 5] = a0; r1[t >> 5] = a1; }
    __syncthreads();
    if (t == 0) {
        float o0 = bd[0], o1 = bd[1];
#pragma unroll
        for (int i = 0; i < 8; i++) { o0 += r0[i]; o1 += r1[i]; }
        out[b * 2]     = o0;
        out[b * 2 + 1] = o1;
    }
}

// ---------------------------------------------------------------------------
// launch
// ---------------------------------------------------------------------------
extern "C" void kernel_launch(void* const* d_in, const int* in_sizes, int n_in,
                              void* d_out, int out_size) {
    const int*   sentence = (const int*)d_in[0];
    const int*   lens     = (const int*)d_in[1];
    const float* emb      = (const float*)d_in[2];
    const float* Wihf     = (const float*)d_in[3];
    const float* Whhf     = (const float*)d_in[4];
    const float* bf       = (const float*)d_in[5];
    const float* Wihb     = (const float*)d_in[6];
    const float* Whhb     = (const float*)d_in[7];
    const float* bb       = (const float*)d_in[8];
    const float* Wd       = (const float*)d_in[9];
    const float* bd       = (const float*)d_in[10];
    float* out = (float*)d_out;

    cudaFuncSetAttribute(lstm_kernel, cudaFuncAttributeMaxDynamicSharedMemorySize, LSTM_SMEM);

    proj_kernel<<<dim3(Vn, 2), 512>>>(emb, Wihf, bf, Wihb, bb);
    lstm_kernel<<<128, 256, LSTM_SMEM>>>(sentence, lens, Whhf, Whhb);
    dense_kernel<<<Bn, 256>>>(Wd, bd, out);
}

// round 8
// speedup vs baseline: 1.2197x; 1.2197x over previous
#include <cuda_runtime.h>
#include <cstdint>

// Problem constants
#define Tn   2048
#define Bn   64
#define Vn   4096
#define En   128
#define H2n  128
#define Sn   8

// Scratch (no allocations allowed)
__device__ float g_proj[2][Vn * 512];      // proj[d][v][gate] = W_ih_d @ emb[v] + b_d (16 MB, L2-resident)
__device__ float g_pooled[Bn * Sn * 256];  // pooled[b][s][h]  (512 KB)

// ---------------------------------------------------------------------------
// helpers
// ---------------------------------------------------------------------------
__device__ __forceinline__ unsigned long long ffma2(unsigned long long a,
                                                    unsigned long long b,
                                                    unsigned long long c) {
    unsigned long long d;
    asm("fma.rn.f32x2 %0, %1, %2, %3;" : "=l"(d) : "l"(a), "l"(b), "l"(c));
    return d;
}
__device__ __forceinline__ float2 unpack2(unsigned long long u) {
    float2 f;
    f.x = __uint_as_float((unsigned)(u & 0xffffffffull));
    f.y = __uint_as_float((unsigned)(u >> 32));
    return f;
}
__device__ __forceinline__ float sigm(float x) {
    return __fdividef(1.f, 1.f + __expf(-x));
}

// ---------------------------------------------------------------------------
// Kernel A: proj[d][v][j] = dot(emb[v], W_ih_d[j]) + b_d[j]
// grid (256, 2) x 512 threads. Thread j owns gate row j; 16 v per block.
// Row weights: first 64 floats in regs (32 f32x2), last 64 staged once in smem.
// ---------------------------------------------------------------------------
#define PROJ_SMEM (16 * 512 * 16 + 16 * 32 * 16)   // sW2[16][512] ul2 + xs2[16][32] ul2 = 139264 B

__global__ void __launch_bounds__(512, 1)
proj_kernel(const float* __restrict__ emb,
            const float* __restrict__ Wf, const float* __restrict__ bf,
            const float* __restrict__ Wb, const float* __restrict__ bb) {
    extern __shared__ ulonglong2 psm[];
    ulonglong2 (*sW2)[512] = (ulonglong2 (*)[512])psm;           // [16][512]
    ulonglong2* xs2 = psm + 16 * 512;                            // [16 v][32]

    int vt = blockIdx.x * 16, d = blockIdx.y, j = threadIdx.x;
    const float* W    = d ? Wb : Wf;
    const float* bias = d ? bb : bf;
    float* outp = g_proj[d];

    // W row j: 32 ulonglong2; first 16 -> regs, last 16 -> smem
    unsigned long long wr[32];
    {
        const ulonglong2* pw = (const ulonglong2*)(W + j * En);
#pragma unroll
        for (int q = 0; q < 16; q++) {
            ulonglong2 t = pw[q];
            wr[2 * q] = t.x; wr[2 * q + 1] = t.y;
        }
#pragma unroll
        for (int q = 0; q < 16; q++) sW2[q][j] = pw[16 + q];
    }
    // x tile: 16 v x 128 floats = 512 float4, one per thread
    {
        int v = j >> 5, kq = j & 31;
        const float4* ev = (const float4*)(emb + (vt + v) * En);
        float4 e = ev[kq];
        ulonglong2 u;
        u.x = ((unsigned long long)__float_as_uint(e.y) << 32) | __float_as_uint(e.x);
        u.y = ((unsigned long long)__float_as_uint(e.w) << 32) | __float_as_uint(e.z);
        xs2[v * 32 + kq] = u;
    }
    __syncthreads();

    float bj = bias[j];
    for (int v = 0; v < 16; v++) {
        const ulonglong2* xv = xs2 + v * 32;
        unsigned long long acc0 = 0, acc1 = 0;
#pragma unroll
        for (int e2 = 0; e2 < 16; e2++) {
            ulonglong2 hx = xv[e2];                  // broadcast
            acc0 = ffma2(wr[2 * e2], hx.x, acc0);
            acc1 = ffma2(wr[2 * e2 + 1], hx.y, acc1);
        }
#pragma unroll
        for (int e2 = 16; e2 < 32; e2++) {
            ulonglong2 hx = xv[e2];
            ulonglong2 wv = sW2[e2 - 16][j];
            acc0 = ffma2(wv.x, hx.x, acc0);
            acc1 = ffma2(wv.y, hx.y, acc1);
        }
        float2 f0 = unpack2(acc0), f1 = unpack2(acc1);
        outp[(vt + v) * 512 + j] = (f0.x + f0.y) + (f1.x + f1.y) + bj;
    }
}

// ---------------------------------------------------------------------------
// Kernel B: recurrent biLSTM with fused ragged max-pool.
// grid 128 = (sample, direction); 256 threads.
// Thread k = 2j+p:  p=0 -> gate rows (i_j = j,     g_j = 256+j)
//                   p=1 -> gate rows (f_j = 128+j, o_j = 384+j)
// sig(i)*tanh(g) crosses lanes via shfl_xor(1); ONE __syncthreads per step.
// Row X fully in regs (64 f32x2); row Y: 32 f32x2 regs + 16 ulonglong2 smem.
// ---------------------------------------------------------------------------
#define NREGW 32
#define LSTM_SMEM (16 * 256 * 16 + 128 * 4 + Sn * 128 * 4)   // 70144 B

__global__ void __launch_bounds__(256, 1)
lstm_kernel(const int* __restrict__ sentence, const int* __restrict__ lens,
            const float* __restrict__ Whhf, const float* __restrict__ Whhb) {
    extern __shared__ ulonglong2 dsm[];
    ulonglong2 (*sW4)[256] = (ulonglong2 (*)[256])dsm;   // [16][256]
    float* h_s  = (float*)(dsm + 16 * 256);              // 128 floats, 16B aligned
    float* wmax = h_s + 128;                             // [8][128]

    int bid = blockIdx.x;
    int b = bid >> 1, d = bid & 1;
    int L = lens[b];
    int w = (L + 7) >> 3;          // per-sample pooling window
    int k = threadIdx.x;
    int j = k >> 1, p = k & 1;
    int rowX = p ? (128 + j) : j;          // f : i
    int rowY = p ? (384 + j) : (256 + j);  // o : g

    const float* W     = d ? Whhb : Whhf;
    const float* projd = g_proj[d];
    const int*   toks  = sentence + b * Tn;

    // --- load W_hh rows ---
    unsigned long long a[64], bw[2 * NREGW / 2];
    {
        const ulonglong2* pa = (const ulonglong2*)(W + rowX * En);
#pragma unroll
        for (int q = 0; q < 32; q++) {
            ulonglong2 t = pa[q];
            a[2 * q] = t.x; a[2 * q + 1] = t.y;
        }
        const ulonglong2* pb = (const ulonglong2*)(W + rowY * En);
#pragma unroll
        for (int q = 0; q < NREGW / 2; q++) {
            ulonglong2 t = pb[q];
            bw[2 * q] = t.x; bw[2 * q + 1] = t.y;
        }
#pragma unroll
        for (int q = NREGW / 2; q < 32; q++) sW4[q - NREGW / 2][k] = pb[q];
    }
    if (k < 128) h_s[k] = 0.f;
    for (int i = k; i < Sn * 128; i += 256) wmax[i] = -3.402823e38f;
    __syncthreads();

    float c = 0.f;
    int segInit = (L - 1) / w; if (segInit > 7) segInit = 7;
    int seg   = d ? segInit : 0;
    int bndUp = w;
    int bndLo = seg * w;

    // prefetch first xg pair
    int tok0 = toks[d ? (L - 1) : 0];
    float xga = __ldg(projd + tok0 * 512 + rowX);
    float xgb = __ldg(projd + tok0 * 512 + rowY);

    for (int s = 0; s < L; s++) {
        int tt = d ? (L - 1 - s) : s;

        // prefetch next step's input-gate pair (hides L2 latency under the FMA loop)
        int s2   = (s + 1 < L) ? (s + 1) : s;
        int tt2  = d ? (L - 1 - s2) : s2;
        int tok2 = __ldg(toks + tt2);
        float nxa = __ldg(projd + tok2 * 512 + rowX);
        float nxb = __ldg(projd + tok2 * 512 + rowY);

        // --- dot products against h (f32x2 packed FMA) ---
        unsigned long long A0 = 0, A1 = 0, B0 = 0, B1 = 0;
        const ulonglong2* hv = (const ulonglong2*)h_s;
#pragma unroll
        for (int e = 0; e < NREGW / 2; e++) {
            ulonglong2 hp = hv[e];                      // broadcast LDS.128
            A0 = ffma2(a[2 * e],     hp.x, A0);
            A1 = ffma2(a[2 * e + 1], hp.y, A1);
            B0 = ffma2(bw[2 * e],     hp.x, B0);
            B1 = ffma2(bw[2 * e + 1], hp.y, B1);
        }
#pragma unroll
        for (int e = NREGW / 2; e < 32; e++) {
            ulonglong2 hp = hv[e];
            ulonglong2 wv = sW4[e - NREGW / 2][k];
            A0 = ffma2(a[2 * e],     hp.x, A0);
            A1 = ffma2(a[2 * e + 1], hp.y, A1);
            B0 = ffma2(wv.x, hp.x, B0);
            B1 = ffma2(wv.y, hp.y, B1);
        }
        float2 fA0 = unpack2(A0), fA1 = unpack2(A1);
        float2 fB0 = unpack2(B0), fB1 = unpack2(B1);
        float gX = (fA0.x + fA0.y) + (fA1.x + fA1.y) + xga;  // i (p=0) / f (p=1)
        float gY = (fB0.x + fB0.y) + (fB1.x + fB1.y) + xgb;  // g (p=0) / o (p=1)

        // branch-free activations:
        //   p=0: need sig(i), tanh(g) = 2*sig(2g)-1
        //   p=1: need sig(f), sig(o)
        float sX = sigm(gX);
        float u  = p ? gY : (gY + gY);
        float sU = sigm(u);
        float vY = p ? sU : (2.f * sU - 1.f);
        float pv = sX * vY;                         // meaningful on even lanes: sig(i)*tanh(g)
        float pvr = __shfl_xor_sync(0xffffffffu, pv, 1);

        if (p) {
            c = sX * c + pvr;                        // sig(f)*c + sig(i)*tanh(g)
            float hn = sU * (2.f * sigm(c + c) - 1.f);  // sig(o)*tanh(c)
            h_s[j] = hn;
            float* wm = wmax + seg * 128 + j;        // fused max-pool
            *wm = fmaxf(*wm, hn);
        }
        __syncthreads();

        // window-boundary tracking (uniform branch, no per-step division)
        if (d) { if (tt == bndLo && seg > 0) { seg--; bndLo -= w; } }
        else   { if (tt + 1 == bndUp && seg < 7) { seg++; bndUp += w; } }
        xga = nxa; xgb = nxb;
    }

    __syncthreads();
    // epilogue: only window 7 can overlap the zero pad (pad length < 8 <= w)
    bool pad7 = (8 * w > L);
    for (int i = k; i < Sn * 128; i += 256) {
        int s = i >> 7, kk = i & 127;
        float v = wmax[i];
        if (s == 7 && pad7) v = fmaxf(v, 0.f);
        g_pooled[(b * Sn + s) * 256 + d * 128 + kk] = v;
    }
}

// ---------------------------------------------------------------------------
// Kernel C: out[b][c] = b_dense[c] + sum_{s,h} pooled[b][s][h] * W_dense[c][h*8+s]
// ---------------------------------------------------------------------------
__global__ void dense_kernel(const float* __restrict__ Wd, const float* __restrict__ bd,
                             float* __restrict__ out) {
    int b = blockIdx.x, t = threadIdx.x;
    const float* p = g_pooled + b * 2048;
    float a0 = 0.f, a1 = 0.f;
    for (int i = t; i < 2048; i += 256) {
        int s = i >> 8, hh = i & 255;
        float v = p[i];
        a0 += v * Wd[hh * 8 + s];
        a1 += v * Wd[2048 + hh * 8 + s];
    }
#pragma unroll
    for (int o = 16; o > 0; o >>= 1) {
        a0 += __shfl_down_sync(0xffffffffu, a0, o);
        a1 += __shfl_down_sync(0xffffffffu, a1, o);
    }
    __shared__ float r0[8], r1[8];
    if ((t & 31) == 0) { r0[t >> 5] = a0; r1[t >> 5] = a1; }
    __syncthreads();
    if (t == 0) {
        float o0 = bd[0], o1 = bd[1];
#pragma unroll
        for (int i = 0; i < 8; i++) { o0 += r0[i]; o1 += r1[i]; }
        out[b * 2]     = o0;
        out[b * 2 + 1] = o1;
    }
}

// ---------------------------------------------------------------------------
// launch
// ---------------------------------------------------------------------------
extern "C" void kernel_launch(void* const* d_in, const int* in_sizes, int n_in,
                              void* d_out, int out_size) {
    const int*   sentence = (const int*)d_in[0];
    const int*   lens     = (const int*)d_in[1];
    const float* emb      = (const float*)d_in[2];
    const float* Wihf     = (const float*)d_in[3];
    const float* Whhf     = (const float*)d_in[4];
    const float* bf       = (const float*)d_in[5];
    const float* Wihb     = (const float*)d_in[6];
    const float* Whhb     = (const float*)d_in[7];
    const float* bb       = (const float*)d_in[8];
    const float* Wd       = (const float*)d_in[9];
    const float* bd       = (const float*)d_in[10];
    float* out = (float*)d_out;

    cudaFuncSetAttribute(proj_kernel, cudaFuncAttributeMaxDynamicSharedMemorySize, PROJ_SMEM);
    cudaFuncSetAttribute(lstm_kernel, cudaFuncAttributeMaxDynamicSharedMemorySize, LSTM_SMEM);

    proj_kernel<<<dim3(Vn / 16, 2), 512, PROJ_SMEM>>>(emb, Wihf, bf, Wihb, bb);
    lstm_kernel<<<128, 256, LSTM_SMEM>>>(sentence, lens, Whhf, Whhb);
    dense_kernel<<<Bn, 256>>>(Wd, bd, out);
}

// round 9
// speedup vs baseline: 1.3227x; 1.0845x over previous
#include <cuda_runtime.h>
#include <cstdint>

// Problem constants
#define Tn   2048
#define Bn   64
#define Vn   4096
#define En   128
#define H2n  128
#define Sn   8

// Scratch (no allocations allowed)
__device__ float g_proj[2][Vn * 512];      // proj[d][v][gate] = W_ih_d @ emb[v] + b_d (16 MB, L2-resident)
__device__ float g_pooled[Bn * Sn * 256];  // pooled[b][s][h]  (512 KB)

// ---------------------------------------------------------------------------
// helpers
// ---------------------------------------------------------------------------
__device__ __forceinline__ unsigned long long ffma2(unsigned long long a,
                                                    unsigned long long b,
                                                    unsigned long long c) {
    unsigned long long d;
    asm("fma.rn.f32x2 %0, %1, %2, %3;" : "=l"(d) : "l"(a), "l"(b), "l"(c));
    return d;
}
__device__ __forceinline__ float2 unpack2(unsigned long long u) {
    float2 f;
    f.x = __uint_as_float((unsigned)(u & 0xffffffffull));
    f.y = __uint_as_float((unsigned)(u >> 32));
    return f;
}

// ---------------------------------------------------------------------------
// Kernel A: proj[d][v][r] = dot(emb[v], W_ih_d[r]) + b_d[r]
// grid (32, 4): y -> (dir, row-half). 256 threads; thread j owns row r = half*256+j,
// ALL 128 row weights in registers (64 f32x2). 128 v per block, x via smem broadcast.
// ---------------------------------------------------------------------------
#define PROJ_VT 128
#define PROJ_SMEM (PROJ_VT * En * 4)   // 65536 B

__global__ void __launch_bounds__(256, 1)
proj_kernel(const float* __restrict__ emb,
            const float* __restrict__ Wf, const float* __restrict__ bf,
            const float* __restrict__ Wb, const float* __restrict__ bb) {
    extern __shared__ float xs[];   // [128 v][128 e]
    int vt   = blockIdx.x * PROJ_VT;
    int d    = blockIdx.y >> 1;
    int half = blockIdx.y & 1;
    int j    = threadIdx.x;
    int r    = half * 256 + j;

    const float* W    = d ? Wb : Wf;
    const float* bias = d ? bb : bf;
    float* outp = g_proj[d];

    // stage x tile: 128 v x 128 floats, coalesced float4
    {
        const float4* src = (const float4*)(emb + vt * En);
        float4* dst = (float4*)xs;
        for (int i = j; i < PROJ_VT * En / 4; i += 256) dst[i] = src[i];
    }

    // row weights fully in regs: 64 f32x2
    unsigned long long wr[64];
    {
        const ulonglong2* pw = (const ulonglong2*)(W + r * En);
#pragma unroll
        for (int q = 0; q < 32; q++) {
            ulonglong2 t = pw[q];
            wr[2 * q] = t.x; wr[2 * q + 1] = t.y;
        }
    }
    float bj = bias[r];
    __syncthreads();

    for (int v = 0; v < PROJ_VT; v++) {
        const ulonglong2* xv = (const ulonglong2*)(xs + v * En);
        unsigned long long acc0 = 0, acc1 = 0, acc2 = 0, acc3 = 0;
#pragma unroll
        for (int q = 0; q < 16; q++) {
            ulonglong2 hx0 = xv[2 * q];
            ulonglong2 hx1 = xv[2 * q + 1];
            acc0 = ffma2(wr[4 * q],     hx0.x, acc0);
            acc1 = ffma2(wr[4 * q + 1], hx0.y, acc1);
            acc2 = ffma2(wr[4 * q + 2], hx1.x, acc2);
            acc3 = ffma2(wr[4 * q + 3], hx1.y, acc3);
        }
        float2 f0 = unpack2(acc0), f1 = unpack2(acc1);
        float2 f2 = unpack2(acc2), f3 = unpack2(acc3);
        outp[(vt + v) * 512 + r] =
            ((f0.x + f0.y) + (f1.x + f1.y)) + ((f2.x + f2.y) + (f3.x + f3.y)) + bj;
    }
}

// ---------------------------------------------------------------------------
// Kernel B: recurrent biLSTM with fused ragged max-pool.
// grid 128 = (sample, direction); 256 threads.
// Pair (2j, 2j+1): thread p owns h-columns [64p, 64p+64) of gate rows
// i_j, f_j, g_j, o_j.  Partial sums combined across the pair with 2 shfl_xor;
// sig(i)*tanh(g) crosses with 1 more shfl. ONE __syncthreads per step.
// Weights: i/f/g halves in regs (96 f32x2 = 192 regs); o half streamed from smem.
// h stored with a 16B pad between halves so even/odd pair reads are conflict-free.
// ---------------------------------------------------------------------------
#define LSTM_SMEM (16 * 256 * 16 + 132 * 4 + Sn * 128 * 4)   // 70160 B

__global__ void __launch_bounds__(256, 1)
lstm_kernel(const int* __restrict__ sentence, const int* __restrict__ lens,
            const float* __restrict__ Whhf, const float* __restrict__ Whhb) {
    extern __shared__ ulonglong2 dsm[];
    ulonglong2 (*sW)[256] = (ulonglong2 (*)[256])dsm;    // [16][256]: o-row halves
    float* h_s  = (float*)(dsm + 16 * 256);              // 132 floats: [0..63],[pad 4],[64..127]
    float* wmax = h_s + 132;                             // [8][128]

    int bid = blockIdx.x;
    int b = bid >> 1, d = bid & 1;
    int L = lens[b];
    int w = (L + 7) >> 3;          // per-sample pooling window (>=128)
    int k = threadIdx.x;
    int j = k >> 1, p = k & 1;

    const float* W     = d ? Whhb : Whhf;
    const float* projd = g_proj[d];
    const int*   toks  = sentence + b * Tn;

    int rX = p ? (128 + j) : j;          // f : i   (xg row for gX)
    int rY = p ? (384 + j) : (256 + j);  // o : g   (xg row for gY)

    // --- load W_hh halves: i/f/g -> regs, o -> smem ---
    unsigned long long wi[32], wf[32], wg[32];
    {
        int co = 64 * p;
        const ulonglong2* pi_ = (const ulonglong2*)(W + j * En + co);
        const ulonglong2* pf_ = (const ulonglong2*)(W + (128 + j) * En + co);
        const ulonglong2* pg_ = (const ulonglong2*)(W + (256 + j) * En + co);
        const ulonglong2* po_ = (const ulonglong2*)(W + (384 + j) * En + co);
#pragma unroll
        for (int q = 0; q < 16; q++) {
            ulonglong2 ti = pi_[q]; wi[2 * q] = ti.x; wi[2 * q + 1] = ti.y;
            ulonglong2 tf = pf_[q]; wf[2 * q] = tf.x; wf[2 * q + 1] = tf.y;
            ulonglong2 tg = pg_[q]; wg[2 * q] = tg.x; wg[2 * q + 1] = tg.y;
            sW[q][k] = po_[q];
        }
    }
    if (k < 132) h_s[k] = 0.f;
    __syncthreads();

    float c = 0.f;
    float rmax = -3.402823e38f;
    int seg   = d ? 7 : 0;       // (L-1)/w == 7 always for L in [1024,2048]
    int bndUp = w;
    int bndLo = 7 * w;
    int hidx  = j + ((j >> 6) << 2);   // padded h index for stores

    // prefetch first xg pair
    int tok0 = toks[d ? (L - 1) : 0];
    float xga = __ldg(projd + tok0 * 512 + rX);
    float xgb = __ldg(projd + tok0 * 512 + rY);

    const ulonglong2* hv = (const ulonglong2*)(h_s + p * 68);

    for (int s = 0; s < L; s++) {
        int tt = d ? (L - 1 - s) : s;

        // prefetch next step's xg pair (hides L2 latency under the FMA loop)
        int s2   = (s + 1 < L) ? (s + 1) : s;
        int tt2  = d ? (L - 1 - s2) : s2;
        int tok2 = __ldg(toks + tt2);
        float nxa = __ldg(projd + tok2 * 512 + rX);
        float nxb = __ldg(projd + tok2 * 512 + rY);

        // --- 4 half-row dots against this thread's h half ---
        unsigned long long Pi0 = 0, Pi1 = 0, Pf0 = 0, Pf1 = 0;
        unsigned long long Pg0 = 0, Pg1 = 0, Po0 = 0, Po1 = 0;
#pragma unroll
        for (int q = 0; q < 16; q++) {
            ulonglong2 hp = hv[q];              // 2-addr (even/odd) bank-disjoint LDS.128
            ulonglong2 wo = sW[q][k];
            Pi0 = ffma2(wi[2 * q],     hp.x, Pi0);
            Pi1 = ffma2(wi[2 * q + 1], hp.y, Pi1);
            Pf0 = ffma2(wf[2 * q],     hp.x, Pf0);
            Pf1 = ffma2(wf[2 * q + 1], hp.y, Pf1);
            Pg0 = ffma2(wg[2 * q],     hp.x, Pg0);
            Pg1 = ffma2(wg[2 * q + 1], hp.y, Pg1);
            Po0 = ffma2(wo.x,          hp.x, Po0);
            Po1 = ffma2(wo.y,          hp.y, Po1);
        }
        float2 a0 = unpack2(Pi0), a1 = unpack2(Pi1);
        float pi = (a0.x + a0.y) + (a1.x + a1.y);
        float2 b0 = unpack2(Pf0), b1 = unpack2(Pf1);
        float pf = (b0.x + b0.y) + (b1.x + b1.y);
        float2 c0 = unpack2(Pg0), c1 = unpack2(Pg1);
        float pg = (c0.x + c0.y) + (c1.x + c1.y);
        float2 d0 = unpack2(Po0), d1 = unpack2(Po1);
        float po = (d0.x + d0.y) + (d1.x + d1.y);

        // combine partials across the pair: even keeps i,g; odd keeps f,o
        float sendA = p ? pi : pf;
        float sendB = p ? pg : po;
        float recvA = __shfl_xor_sync(0xffffffffu, sendA, 1);
        float recvB = __shfl_xor_sync(0xffffffffu, sendB, 1);
        float gX = (p ? pf : pi) + recvA + xga;   // i (even) / f (odd)
        float gY = (p ? po : pg) + recvB + xgb;   // g (even) / o (odd)

        // activations (R6 numerics): sigm(x)=1/(1+e^-x); tanh(x)=1-2/(e^2x+1)
        float vX = __fdividef(1.f, 1.f + __expf(-gX));         // sig(i)/sig(f)
        float eY = __expf(p ? -gY : (gY + gY));
        float fr = __fdividef(p ? 1.f : 2.f, 1.f + eY);
        float vY = p ? fr : (1.f - fr);                        // tanh(g)/sig(o)

        float pvr = __shfl_xor_sync(0xffffffffu, vX * vY, 1);  // sig(i)*tanh(g) -> odd

        c = vX * c + pvr;                                      // meaningful on odd lanes
        float tc = 1.f - __fdividef(2.f, __expf(c + c) + 1.f); // tanh(c)
        float hn = vY * tc;                                    // sig(o)*tanh(c)
        if (p) {
            h_s[hidx] = hn;
            rmax = fmaxf(rmax, hn);
        }
        __syncthreads();

        // pooling-window boundary: flush register max (7 crossings per chain)
        if (d) {
            if (tt == bndLo && seg > 0) {
                if (p) wmax[seg * 128 + j] = rmax;
                rmax = -3.402823e38f; seg--; bndLo -= w;
            }
        } else {
            if (tt + 1 == bndUp && seg < 7) {
                if (p) wmax[seg * 128 + j] = rmax;
                rmax = -3.402823e38f; seg++; bndUp += w;
            }
        }
        xga = nxa; xgb = nxb;
    }
    if (p) wmax[seg * 128 + j] = rmax;   // final segment
    __syncthreads();

    // epilogue: only window 7 can overlap the zero pad (pad length < 8 <= w)
    bool pad7 = (8 * w > L);
    for (int i = k; i < Sn * 128; i += 256) {
        int s = i >> 7, kk = i & 127;
        float v = wmax[i];
        if (s == 7 && pad7) v = fmaxf(v, 0.f);
        g_pooled[(b * Sn + s) * 256 + d * 128 + kk] = v;
    }
}

// ---------------------------------------------------------------------------
// Kernel C: out[b][c] = b_dense[c] + sum_{s,h} pooled[b][s][h] * W_dense[c][h*8+s]
// ---------------------------------------------------------------------------
__global__ void dense_kernel(const float* __restrict__ Wd, const float* __restrict__ bd,
                             float* __restrict__ out) {
    int b = blockIdx.x, t = threadIdx.x;
    const float* p = g_pooled + b * 2048;
    float a0 = 0.f, a1 = 0.f;
    for (int i = t; i < 2048; i += 256) {
        int s = i >> 8, hh = i & 255;
        float v = p[i];
        a0 += v * Wd[hh * 8 + s];
        a1 += v * Wd[2048 + hh * 8 + s];
    }
#pragma unroll
    for (int o = 16; o > 0; o >>= 1) {
        a0 += __shfl_down_sync(0xffffffffu, a0, o);
        a1 += __shfl_down_sync(0xffffffffu, a1, o);
    }
    __shared__ float r0[8], r1[8];
    if ((t & 31) == 0) { r0[t >> 5] = a0; r1[t >> 5] = a1; }
    __syncthreads();
    if (t == 0) {
        float o0 = bd[0], o1 = bd[1];
#pragma unroll
        for (int i = 0; i < 8; i++) { o0 += r0[i]; o1 += r1[i]; }
        out[b * 2]     = o0;
        out[b * 2 + 1] = o1;
    }
}

// ---------------------------------------------------------------------------
// launch
// ---------------------------------------------------------------------------
extern "C" void kernel_launch(void* const* d_in, const int* in_sizes, int n_in,
                              void* d_out, int out_size) {
    const int*   sentence = (const int*)d_in[0];
    const int*   lens     = (const int*)d_in[1];
    const float* emb      = (const float*)d_in[2];
    const float* Wihf     = (const float*)d_in[3];
    const float* Whhf     = (const float*)d_in[4];
    const float* bf       = (const float*)d_in[5];
    const float* Wihb     = (const float*)d_in[6];
    const float* Whhb     = (const float*)d_in[7];
    const float* bb       = (const float*)d_in[8];
    const float* Wd       = (const float*)d_in[9];
    const float* bd       = (const float*)d_in[10];
    float* out = (float*)d_out;

    cudaFuncSetAttribute(proj_kernel, cudaFuncAttributeMaxDynamicSharedMemorySize, PROJ_SMEM);
    cudaFuncSetAttribute(lstm_kernel, cudaFuncAttributeMaxDynamicSharedMemorySize, LSTM_SMEM);

    proj_kernel<<<dim3(Vn / PROJ_VT, 4), 256, PROJ_SMEM>>>(emb, Wihf, bf, Wihb, bb);
    lstm_kernel<<<128, 256, LSTM_SMEM>>>(sentence, lens, Whhf, Whhb);
    dense_kernel<<<Bn, 256>>>(Wd, bd, out);
}

// round 10
// speedup vs baseline: 1.7185x; 1.2992x over previous
#include <cuda_runtime.h>
#include <cstdint>

// Problem constants
#define Tn   2048
#define Bn   64
#define Vn   4096
#define En   128
#define H2n  128
#define Sn   8

// Scratch (no allocations allowed)
__device__ float g_proj[2][Vn * 512];      // proj[d][v][gate] = W_ih_d @ emb[v] + b_d (16 MB, L2-resident)
__device__ float g_pooled[Bn * Sn * 256];  // pooled[b][s][h]  (512 KB)

// ---------------------------------------------------------------------------
// helpers
// ---------------------------------------------------------------------------
__device__ __forceinline__ unsigned long long ffma2(unsigned long long a,
                                                    unsigned long long b,
                                                    unsigned long long c) {
    unsigned long long d;
    asm("fma.rn.f32x2 %0, %1, %2, %3;" : "=l"(d) : "l"(a), "l"(b), "l"(c));
    return d;
}
__device__ __forceinline__ float2 unpack2(unsigned long long u) {
    float2 f;
    f.x = __uint_as_float((unsigned)(u & 0xffffffffull));
    f.y = __uint_as_float((unsigned)(u >> 32));
    return f;
}
__device__ __forceinline__ float ex2f(float x) {
    float y; asm("ex2.approx.f32 %0, %1;" : "=f"(y) : "f"(x)); return y;
}
__device__ __forceinline__ float rcpf(float x) {
    float y; asm("rcp.approx.f32 %0, %1;" : "=f"(y) : "f"(x)); return y;
}
#define LOG2E 1.4426950408889634f

// ---------------------------------------------------------------------------
// Kernel A: proj[d][v][r] = dot(emb[v], W_ih_d[r]) + b_d[r]
// grid (32, 4): y -> (dir, row-half). 256 threads; thread j owns row r = half*256+j,
// ALL 128 row weights in registers (64 f32x2). 128 v per block, x via smem broadcast.
// ---------------------------------------------------------------------------
#define PROJ_VT 128
#define PROJ_SMEM (PROJ_VT * En * 4)   // 65536 B

__global__ void __launch_bounds__(256, 1)
proj_kernel(const float* __restrict__ emb,
            const float* __restrict__ Wf, const float* __restrict__ bf,
            const float* __restrict__ Wb, const float* __restrict__ bb) {
    extern __shared__ float xs[];   // [128 v][128 e]
    int vt   = blockIdx.x * PROJ_VT;
    int d    = blockIdx.y >> 1;
    int half = blockIdx.y & 1;
    int j    = threadIdx.x;
    int r    = half * 256 + j;

    const float* W    = d ? Wb : Wf;
    const float* bias = d ? bb : bf;
    float* outp = g_proj[d];

    // stage x tile: 128 v x 128 floats, coalesced float4
    {
        const float4* src = (const float4*)(emb + vt * En);
        float4* dst = (float4*)xs;
        for (int i = j; i < PROJ_VT * En / 4; i += 256) dst[i] = src[i];
    }

    // row weights fully in regs: 64 f32x2
    unsigned long long wr[64];
    {
        const ulonglong2* pw = (const ulonglong2*)(W + r * En);
#pragma unroll
        for (int q = 0; q < 32; q++) {
            ulonglong2 t = pw[q];
            wr[2 * q] = t.x; wr[2 * q + 1] = t.y;
        }
    }
    float bj = bias[r];
    __syncthreads();

    for (int v = 0; v < PROJ_VT; v++) {
        const ulonglong2* xv = (const ulonglong2*)(xs + v * En);
        unsigned long long acc0 = 0, acc1 = 0, acc2 = 0, acc3 = 0;
#pragma unroll
        for (int q = 0; q < 16; q++) {
            ulonglong2 hx0 = xv[2 * q];
            ulonglong2 hx1 = xv[2 * q + 1];
            acc0 = ffma2(wr[4 * q],     hx0.x, acc0);
            acc1 = ffma2(wr[4 * q + 1], hx0.y, acc1);
            acc2 = ffma2(wr[4 * q + 2], hx1.x, acc2);
            acc3 = ffma2(wr[4 * q + 3], hx1.y, acc3);
        }
        float2 f0 = unpack2(acc0), f1 = unpack2(acc1);
        float2 f2 = unpack2(acc2), f3 = unpack2(acc3);
        outp[(vt + v) * 512 + r] =
            ((f0.x + f0.y) + (f1.x + f1.y)) + ((f2.x + f2.y) + (f3.x + f3.y)) + bj;
    }
}

// ---------------------------------------------------------------------------
// Kernel B: recurrent biLSTM with fused ragged max-pool.
// grid 128 = (sample, direction); 256 threads.
// Pair (2j, 2j+1): thread p owns h-columns [64p, 64p+64) of gate rows
// i_j, f_j, g_j, o_j. One f32x2 accumulator per gate; pair partials combined
// via 2 shfl_xor; sig(i)*tanh(g) crosses with 1 more shfl. ONE barrier per step.
// Weights: i/f/g halves in regs (96 f32x2), o half: 4 ul2 regs + 12 ul2 smem.
// Pooling boundaries via countdown counter; per-seg max in a register.
// ---------------------------------------------------------------------------
#define OSW 12
#define LSTM_SMEM (OSW * 256 * 16 + 132 * 4 + Sn * 128 * 4)   // 53776 B

__global__ void __launch_bounds__(256, 1)
lstm_kernel(const int* __restrict__ sentence, const int* __restrict__ lens,
            const float* __restrict__ Whhf, const float* __restrict__ Whhb) {
    extern __shared__ ulonglong2 dsm[];
    ulonglong2 (*sW)[256] = (ulonglong2 (*)[256])dsm;    // [12][256]: o-row tail
    float* h_s  = (float*)(dsm + OSW * 256);             // 132 floats: [0..63],[pad 4],[64..127]
    float* wmax = h_s + 132;                             // [8][128]

    int bid = blockIdx.x;
    int b = bid >> 1, d = bid & 1;
    int L = lens[b];
    int w = (L + 7) >> 3;          // pooling window (>=128 for L in [1024,2048])
    int k = threadIdx.x;
    int j = k >> 1, p = k & 1;

    const float* W     = d ? Whhb : Whhf;
    const float* projd = g_proj[d];
    const int*   toks  = sentence + b * Tn;

    int rX = p ? (128 + j) : j;          // f : i   (xg row for gX)
    int rY = p ? (384 + j) : (256 + j);  // o : g   (xg row for gY)

    // --- load W_hh halves: i/f/g -> regs; o: first 4 ul2 -> regs, rest -> smem ---
    unsigned long long wi[32], wf[32], wg[32], wo[8];
    {
        int co = 64 * p;
        const ulonglong2* pi_ = (const ulonglong2*)(W + j * En + co);
        const ulonglong2* pf_ = (const ulonglong2*)(W + (128 + j) * En + co);
        const ulonglong2* pg_ = (const ulonglong2*)(W + (256 + j) * En + co);
        const ulonglong2* po_ = (const ulonglong2*)(W + (384 + j) * En + co);
#pragma unroll
        for (int q = 0; q < 16; q++) {
            ulonglong2 ti = pi_[q]; wi[2 * q] = ti.x; wi[2 * q + 1] = ti.y;
            ulonglong2 tf = pf_[q]; wf[2 * q] = tf.x; wf[2 * q + 1] = tf.y;
            ulonglong2 tg = pg_[q]; wg[2 * q] = tg.x; wg[2 * q + 1] = tg.y;
        }
#pragma unroll
        for (int q = 0; q < 4; q++) {
            ulonglong2 to = po_[q]; wo[2 * q] = to.x; wo[2 * q + 1] = to.y;
        }
#pragma unroll
        for (int q = 4; q < 16; q++) sW[q - 4][k] = po_[q];
    }
    if (k < 132) h_s[k] = 0.f;
    __syncthreads();

    float c = 0.f;
    float rmax = -3.402823e38f;
    int sdir = d ? -1 : 1;
    int seg  = d ? 7 : 0;                  // (L-1)/w == 7 for all valid L
    int cnt  = d ? (L - 7 * w) : w;        // steps until current segment closes
    int hidx = j + ((j >> 6) << 2);        // padded h index for stores
    int idx  = d ? (L - 1) : 0;            // current time index

    // prefetch first xg pair
    int tok0 = toks[idx];
    float xga = __ldg(projd + tok0 * 512 + rX);
    float xgb = __ldg(projd + tok0 * 512 + rY);

    const ulonglong2* hv = (const ulonglong2*)(h_s + p * 68);

    for (int s = 0; s < L; s++) {
        // prefetch next step's xg pair (hides L2 latency under the FMA loop)
        int ni = idx + sdir;
        ni = ni < 0 ? 0 : (ni >= L ? L - 1 : ni);
        int tok2 = __ldg(toks + ni);
        float nxa = __ldg(projd + tok2 * 512 + rX);
        float nxb = __ldg(projd + tok2 * 512 + rY);

        // --- 4 half-row dots against this thread's h half (1 f32x2 acc each) ---
        unsigned long long Pi = 0, Pf = 0, Pg = 0, Po = 0;
#pragma unroll
        for (int q = 0; q < 16; q++) {
            ulonglong2 hp = hv[q];              // 2-addr (even/odd) bank-disjoint LDS.128
            unsigned long long wox, woy;
            if (q < 4) { wox = wo[2 * q]; woy = wo[2 * q + 1]; }
            else       { ulonglong2 t = sW[q - 4][k]; wox = t.x; woy = t.y; }
            Pi = ffma2(wi[2 * q],     hp.x, Pi);
            Pi = ffma2(wi[2 * q + 1], hp.y, Pi);
            Pf = ffma2(wf[2 * q],     hp.x, Pf);
            Pf = ffma2(wf[2 * q + 1], hp.y, Pf);
            Pg = ffma2(wg[2 * q],     hp.x, Pg);
            Pg = ffma2(wg[2 * q + 1], hp.y, Pg);
            Po = ffma2(wox,           hp.x, Po);
            Po = ffma2(woy,           hp.y, Po);
        }
        float2 vi_ = unpack2(Pi); float pi = vi_.x + vi_.y;
        float2 vf_ = unpack2(Pf); float pf = vf_.x + vf_.y;
        float2 vg_ = unpack2(Pg); float pg = vg_.x + vg_.y;
        float2 vo_ = unpack2(Po); float po = vo_.x + vo_.y;

        // combine partials across the pair: even keeps i,g; odd keeps f,o
        float sendA = p ? pi : pf;
        float sendB = p ? pg : po;
        float recvA = __shfl_xor_sync(0xffffffffu, sendA, 1);
        float recvB = __shfl_xor_sync(0xffffffffu, sendB, 1);
        float gX = (p ? pf : pi) + recvA + xga;   // i (even) / f (odd)
        float gY = (p ? po : pg) + recvB + xgb;   // g (even) / o (odd)

        // activations: sigm(x) = rcp(1 + 2^(-x*log2e));  tanh(x) = 1 - 2*rcp(1 + 2^(2x*log2e))
        float vX = rcpf(1.f + ex2f(gX * -LOG2E));              // sig(i)/sig(f)
        float sc = p ? -LOG2E : (2.f * LOG2E);
        float rr = rcpf(1.f + ex2f(gY * sc));
        float vY = p ? rr : fmaf(-2.f, rr, 1.f);               // sig(o)/tanh(g)

        float pvr = __shfl_xor_sync(0xffffffffu, vX * vY, 1);  // sig(i)*tanh(g) -> odd

        c = vX * c + pvr;                                      // meaningful on odd lanes
        float tc = fmaf(-2.f, rcpf(1.f + ex2f(c * (2.f * LOG2E))), 1.f);  // tanh(c)
        float hn = vY * tc;                                    // sig(o)*tanh(c)
        if (p) {
            h_s[hidx] = hn;
            rmax = fmaxf(rmax, hn);
        }
        __syncthreads();

        // segment boundary: flush register max (7-8 crossings per chain)
        if (--cnt == 0) {
            if (p) wmax[seg * 128 + j] = rmax;
            rmax = -3.402823e38f;
            seg += sdir;
            cnt = w;
        }
        idx = ni;
        xga = nxa; xgb = nxb;
    }
    if (cnt != w && p) wmax[seg * 128 + j] = rmax;   // pending partial segment
    __syncthreads();

    // epilogue: only window 7 can overlap the zero pad (pad length < 8 <= w)
    bool pad7 = (8 * w > L);
    for (int i = k; i < Sn * 128; i += 256) {
        int s = i >> 7, kk = i & 127;
        float v = wmax[i];
        if (s == 7 && pad7) v = fmaxf(v, 0.f);
        g_pooled[(b * Sn + s) * 256 + d * 128 + kk] = v;
    }
}

// ---------------------------------------------------------------------------
// Kernel C: out[b][c] = b_dense[c] + sum_{s,h} pooled[b][s][h] * W_dense[c][h*8+s]
// ---------------------------------------------------------------------------
__global__ void dense_kernel(const float* __restrict__ Wd, const float* __restrict__ bd,
                             float* __restrict__ out) {
    int b = blockIdx.x, t = threadIdx.x;
    const float* p = g_pooled + b * 2048;
    float a0 = 0.f, a1 = 0.f;
    for (int i = t; i < 2048; i += 256) {
        int s = i >> 8, hh = i & 255;
        float v = p[i];
        a0 += v * Wd[hh * 8 + s];
        a1 += v * Wd[2048 + hh * 8 + s];
    }
#pragma unroll
    for (int o = 16; o > 0; o >>= 1) {
        a0 += __shfl_down_sync(0xffffffffu, a0, o);
        a1 += __shfl_down_sync(0xffffffffu, a1, o);
    }
    __shared__ float r0[8], r1[8];
    if ((t & 31) == 0) { r0[t >> 5] = a0; r1[t >> 5] = a1; }
    __syncthreads();
    if (t == 0) {
        float o0 = bd[0], o1 = bd[1];
#pragma unroll
        for (int i = 0; i < 8; i++) { o0 += r0[i]; o1 += r1[i]; }
        out[b * 2]     = o0;
        out[b * 2 + 1] = o1;
    }
}

// ---------------------------------------------------------------------------
// launch
// ---------------------------------------------------------------------------
extern "C" void kernel_launch(void* const* d_in, const int* in_sizes, int n_in,
                              void* d_out, int out_size) {
    const int*   sentence = (const int*)d_in[0];
    const int*   lens     = (const int*)d_in[1];
    const float* emb      = (const float*)d_in[2];
    const float* Wihf     = (const float*)d_in[3];
    const float* Whhf     = (const float*)d_in[4];
    const float* bf       = (const float*)d_in[5];
    const float* Wihb     = (const float*)d_in[6];
    const float* Whhb     = (const float*)d_in[7];
    const float* bb       = (const float*)d_in[8];
    const float* Wd       = (const float*)d_in[9];
    const float* bd       = (const float*)d_in[10];
    float* out = (float*)d_out;

    cudaFuncSetAttribute(proj_kernel, cudaFuncAttributeMaxDynamicSharedMemorySize, PROJ_SMEM);
    cudaFuncSetAttribute(lstm_kernel, cudaFuncAttributeMaxDynamicSharedMemorySize, LSTM_SMEM);

    proj_kernel<<<dim3(Vn / PROJ_VT, 4), 256, PROJ_SMEM>>>(emb, Wihf, bf, Wihb, bb);
    lstm_kernel<<<128, 256, LSTM_SMEM>>>(sentence, lens, Whhf, Whhb);
    dense_kernel<<<Bn, 256>>>(Wd, bd, out);
}

// round 11
// speedup vs baseline: 1.7695x; 1.0297x over previous
#include <cuda_runtime.h>
#include <cstdint>

// Problem constants
#define Tn   2048
#define Bn   64
#define Vn   4096
#define En   128
#define H2n  128
#define Sn   8

// Scratch (no allocations allowed)
__device__ float g_proj[2][Vn * 512];      // proj[d][v][gate] = W_ih_d @ emb[v] + b_d (16 MB, L2-resident)
__device__ float g_pooled[Bn * Sn * 256];  // pooled[b][s][h]  (512 KB)

// ---------------------------------------------------------------------------
// helpers
// ---------------------------------------------------------------------------
__device__ __forceinline__ unsigned long long ffma2(unsigned long long a,
                                                    unsigned long long b,
                                                    unsigned long long c) {
    unsigned long long d;
    asm("fma.rn.f32x2 %0, %1, %2, %3;" : "=l"(d) : "l"(a), "l"(b), "l"(c));
    return d;
}
__device__ __forceinline__ float2 unpack2(unsigned long long u) {
    float2 f;
    f.x = __uint_as_float((unsigned)(u & 0xffffffffull));
    f.y = __uint_as_float((unsigned)(u >> 32));
    return f;
}
__device__ __forceinline__ float ex2f(float x) {
    float y; asm("ex2.approx.f32 %0, %1;" : "=f"(y) : "f"(x)); return y;
}
__device__ __forceinline__ float rcpf(float x) {
    float y; asm("rcp.approx.f32 %0, %1;" : "=f"(y) : "f"(x)); return y;
}
__device__ __forceinline__ float tanhf_fast(float x) {
    float y; asm("tanh.approx.f32 %0, %1;" : "=f"(y) : "f"(x)); return y;
}
#define LOG2E 1.4426950408889634f

// ---------------------------------------------------------------------------
// Kernel A: proj[d][v][r] = dot(emb[v], W_ih_d[r]) + b_d[r]
// grid (32, 4): y -> (dir, row-half). 256 threads; thread j owns row r = half*256+j,
// ALL 128 row weights in registers (64 f32x2). 128 v per block, 2 v per iter (ILP).
// ---------------------------------------------------------------------------
#define PROJ_VT 128
#define PROJ_SMEM (PROJ_VT * En * 4)   // 65536 B

__global__ void __launch_bounds__(256, 1)
proj_kernel(const float* __restrict__ emb,
            const float* __restrict__ Wf, const float* __restrict__ bf,
            const float* __restrict__ Wb, const float* __restrict__ bb) {
    extern __shared__ float xs[];   // [128 v][128 e]
    int vt   = blockIdx.x * PROJ_VT;
    int d    = blockIdx.y >> 1;
    int half = blockIdx.y & 1;
    int j    = threadIdx.x;
    int r    = half * 256 + j;

    const float* W    = d ? Wb : Wf;
    const float* bias = d ? bb : bf;
    float* outp = g_proj[d];

    // stage x tile: 128 v x 128 floats, coalesced float4
    {
        const float4* src = (const float4*)(emb + vt * En);
        float4* dst = (float4*)xs;
        for (int i = j; i < PROJ_VT * En / 4; i += 256) dst[i] = src[i];
    }

    // row weights fully in regs: 64 f32x2
    unsigned long long wr[64];
    {
        const ulonglong2* pw = (const ulonglong2*)(W + r * En);
#pragma unroll
        for (int q = 0; q < 32; q++) {
            ulonglong2 t = pw[q];
            wr[2 * q] = t.x; wr[2 * q + 1] = t.y;
        }
    }
    float bj = bias[r];
    __syncthreads();

    for (int v = 0; v < PROJ_VT; v += 2) {
        const ulonglong2* xv0 = (const ulonglong2*)(xs + v * En);
        const ulonglong2* xv1 = (const ulonglong2*)(xs + (v + 1) * En);
        unsigned long long a0 = 0, a1 = 0, a2 = 0, a3 = 0;
        unsigned long long b0 = 0, b1 = 0, b2 = 0, b3 = 0;
#pragma unroll
        for (int q = 0; q < 16; q++) {
            ulonglong2 hx0 = xv0[2 * q];
            ulonglong2 hx1 = xv0[2 * q + 1];
            ulonglong2 gx0 = xv1[2 * q];
            ulonglong2 gx1 = xv1[2 * q + 1];
            a0 = ffma2(wr[4 * q],     hx0.x, a0);
            a1 = ffma2(wr[4 * q + 1], hx0.y, a1);
            a2 = ffma2(wr[4 * q + 2], hx1.x, a2);
            a3 = ffma2(wr[4 * q + 3], hx1.y, a3);
            b0 = ffma2(wr[4 * q],     gx0.x, b0);
            b1 = ffma2(wr[4 * q + 1], gx0.y, b1);
            b2 = ffma2(wr[4 * q + 2], gx1.x, b2);
            b3 = ffma2(wr[4 * q + 3], gx1.y, b3);
        }
        float2 f0 = unpack2(a0), f1 = unpack2(a1);
        float2 f2 = unpack2(a2), f3 = unpack2(a3);
        outp[(vt + v) * 512 + r] =
            ((f0.x + f0.y) + (f1.x + f1.y)) + ((f2.x + f2.y) + (f3.x + f3.y)) + bj;
        float2 g0 = unpack2(b0), g1 = unpack2(b1);
        float2 g2 = unpack2(b2), g3 = unpack2(b3);
        outp[(vt + v + 1) * 512 + r] =
            ((g0.x + g0.y) + (g1.x + g1.y)) + ((g2.x + g2.y) + (g3.x + g3.y)) + bj;
    }
}

// ---------------------------------------------------------------------------
// Kernel B: recurrent biLSTM with fused ragged max-pool.
// grid 128 = (sample, direction); 256 threads.
// Pair (2j, 2j+1): thread p owns h-columns [64p, 64p+64) of gate rows
// i_j, f_j, g_j, o_j. One f32x2 accumulator per gate; pair partials combined
// via 2 shfl_xor; sig(i)*tanh(g) crosses with 1 more shfl. ONE barrier per step.
// tanh(g), tanh(c) via MUFU tanh.approx; sigmoids exact (ex2+rcp).
// Weights: i/f/g halves in regs (96 f32x2), o half: 4 ul2 regs + 12 ul2 smem.
// h double-buffered (removes WAR hazard across the single barrier).
// ---------------------------------------------------------------------------
#define OSW 12
#define LSTM_SMEM (OSW * 256 * 16 + 2 * 136 * 4 + Sn * 128 * 4)   // 54336 B

__global__ void __launch_bounds__(256, 1)
lstm_kernel(const int* __restrict__ sentence, const int* __restrict__ lens,
            const float* __restrict__ Whhf, const float* __restrict__ Whhb) {
    extern __shared__ ulonglong2 dsm[];
    ulonglong2 (*sW)[256] = (ulonglong2 (*)[256])dsm;    // [12][256]: o-row tail
    float* hA   = (float*)(dsm + OSW * 256);             // 136 floats: [0..63],[pad],[64..127],[pad]
    float* hB   = hA + 136;                              // second buffer
    float* wmax = hB + 136;                              // [8][128]

    int bid = blockIdx.x;
    int b = bid >> 1, d = bid & 1;
    int L = lens[b];
    int w = (L + 7) >> 3;          // pooling window (>=128 for L in [1024,2048])
    int k = threadIdx.x;
    int j = k >> 1, p = k & 1;

    const float* W     = d ? Whhb : Whhf;
    const float* projd = g_proj[d];
    const int*   toks  = sentence + b * Tn;

    int rX = p ? (128 + j) : j;          // f : i   (xg row for gX)
    int rY = p ? (384 + j) : (256 + j);  // o : g   (xg row for gY)

    // --- load W_hh halves: i/f/g -> regs; o: first 4 ul2 -> regs, rest -> smem ---
    unsigned long long wi[32], wf[32], wg[32], wo[8];
    {
        int co = 64 * p;
        const ulonglong2* pi_ = (const ulonglong2*)(W + j * En + co);
        const ulonglong2* pf_ = (const ulonglong2*)(W + (128 + j) * En + co);
        const ulonglong2* pg_ = (const ulonglong2*)(W + (256 + j) * En + co);
        const ulonglong2* po_ = (const ulonglong2*)(W + (384 + j) * En + co);
#pragma unroll
        for (int q = 0; q < 16; q++) {
            ulonglong2 ti = pi_[q]; wi[2 * q] = ti.x; wi[2 * q + 1] = ti.y;
            ulonglong2 tf = pf_[q]; wf[2 * q] = tf.x; wf[2 * q + 1] = tf.y;
            ulonglong2 tg = pg_[q]; wg[2 * q] = tg.x; wg[2 * q + 1] = tg.y;
        }
#pragma unroll
        for (int q = 0; q < 4; q++) {
            ulonglong2 to = po_[q]; wo[2 * q] = to.x; wo[2 * q + 1] = to.y;
        }
#pragma unroll
        for (int q = 4; q < 16; q++) sW[q - 4][k] = po_[q];
    }
    if (k < 136) { hA[k] = 0.f; hB[k] = 0.f; }
    __syncthreads();

    float c = 0.f;
    float rmax = -3.402823e38f;
    int sdir = d ? -1 : 1;
    int seg  = d ? 7 : 0;                  // (L-1)/w == 7 for all valid L
    int cnt  = d ? (L - 7 * w) : w;        // steps until current segment closes
    int hidx = j + ((j >> 6) << 2);        // padded h index for stores
    int poff = p * 68;                     // padded read offset for this half
    int idx  = d ? (L - 1) : 0;            // current time index

    float* hr = hA;   // read buffer (h(t-1))
    float* hw = hB;   // write buffer (h(t))

    // prefetch first xg pair
    int tok0 = toks[idx];
    float xga = __ldg(projd + tok0 * 512 + rX);
    float xgb = __ldg(projd + tok0 * 512 + rY);

    for (int s = 0; s < L; s++) {
        // prefetch next step's xg pair (hides L2 latency under the FMA loop)
        int ni = idx + sdir;
        ni = ni < 0 ? 0 : (ni >= L ? L - 1 : ni);
        int tok2 = __ldg(toks + ni);
        float nxa = __ldg(projd + tok2 * 512 + rX);
        float nxb = __ldg(projd + tok2 * 512 + rY);

        // --- 4 half-row dots against this thread's h half (1 f32x2 acc each) ---
        const ulonglong2* hv = (const ulonglong2*)(hr + poff);
        unsigned long long Pi = 0, Pf = 0, Pg = 0, Po = 0;
#pragma unroll
        for (int q = 0; q < 16; q++) {
            ulonglong2 hp = hv[q];              // 2-addr (even/odd) bank-disjoint LDS.128
            unsigned long long wox, woy;
            if (q < 4) { wox = wo[2 * q]; woy = wo[2 * q + 1]; }
            else       { ulonglong2 t = sW[q - 4][k]; wox = t.x; woy = t.y; }
            Pi = ffma2(wi[2 * q],     hp.x, Pi);
            Pi = ffma2(wi[2 * q + 1], hp.y, Pi);
            Pf = ffma2(wf[2 * q],     hp.x, Pf);
            Pf = ffma2(wf[2 * q + 1], hp.y, Pf);
            Pg = ffma2(wg[2 * q],     hp.x, Pg);
            Pg = ffma2(wg[2 * q + 1], hp.y, Pg);
            Po = ffma2(wox,           hp.x, Po);
            Po = ffma2(woy,           hp.y, Po);
        }
        float2 vi_ = unpack2(Pi); float pi = vi_.x + vi_.y;
        float2 vf_ = unpack2(Pf); float pf = vf_.x + vf_.y;
        float2 vg_ = unpack2(Pg); float pg = vg_.x + vg_.y;
        float2 vo_ = unpack2(Po); float po = vo_.x + vo_.y;

        // combine partials across the pair: even keeps i,g; odd keeps f,o
        float sendA = p ? pi : pf;
        float sendB = p ? pg : po;
        float recvA = __shfl_xor_sync(0xffffffffu, sendA, 1);
        float recvB = __shfl_xor_sync(0xffffffffu, sendB, 1);
        float gX = (p ? pf : pi) + recvA + xga;   // i (even) / f (odd)
        float gY = (p ? po : pg) + recvB + xgb;   // g (even) / o (odd)

        // activations: sigmoids exact (ex2+rcp); tanh via MUFU tanh.approx
        float vX = rcpf(1.f + ex2f(gX * -LOG2E));   // sig(i)/sig(f)
        float th = tanhf_fast(gY);                  // tanh(g)   (even lanes use)
        float sg = rcpf(1.f + ex2f(gY * -LOG2E));   // sig(o)    (odd lanes use)
        float vY = p ? sg : th;

        float pvr = __shfl_xor_sync(0xffffffffu, vX * vY, 1);  // sig(i)*tanh(g) -> odd

        c = vX * c + pvr;                           // meaningful on odd lanes
        float hn = vY * tanhf_fast(c);              // sig(o)*tanh(c)
        if (p) {
            hw[hidx] = hn;
            rmax = fmaxf(rmax, hn);
        }
        __syncthreads();

        // segment boundary: flush register max (7-8 crossings per chain)
        if (--cnt == 0) {
            if (p) wmax[seg * 128 + j] = rmax;
            rmax = -3.402823e38f;
            seg += sdir;
            cnt = w;
        }
        idx = ni;
        xga = nxa; xgb = nxb;
        float* t = hr; hr = hw; hw = t;             // swap double buffers
    }
    if (cnt != w && p) wmax[seg * 128 + j] = rmax;   // pending partial segment
    __syncthreads();

    // epilogue: only window 7 can overlap the zero pad (pad length < 8 <= w)
    bool pad7 = (8 * w > L);
    for (int i = k; i < Sn * 128; i += 256) {
        int s = i >> 7, kk = i & 127;
        float v = wmax[i];
        if (s == 7 && pad7) v = fmaxf(v, 0.f);
        g_pooled[(b * Sn + s) * 256 + d * 128 + kk] = v;
    }
}

// ---------------------------------------------------------------------------
// Kernel C: out[b][c] = b_dense[c] + sum_{s,h} pooled[b][s][h] * W_dense[c][h*8+s]
// ---------------------------------------------------------------------------
__global__ void dense_kernel(const float* __restrict__ Wd, const float* __restrict__ bd,
                             float* __restrict__ out) {
    int b = blockIdx.x, t = threadIdx.x;
    const float* p = g_pooled + b * 2048;
    float a0 = 0.f, a1 = 0.f;
    for (int i = t; i < 2048; i += 256) {
        int s = i >> 8, hh = i & 255;
        float v = p[i];
        a0 += v * Wd[hh * 8 + s];
        a1 += v * Wd[2048 + hh * 8 + s];
    }
#pragma unroll
    for (int o = 16; o > 0; o >>= 1) {
        a0 += __shfl_down_sync(0xffffffffu, a0, o);
        a1 += __shfl_down_sync(0xffffffffu, a1, o);
    }
    __shared__ float r0[8], r1[8];
    if ((t & 31) == 0) { r0[t >> 5] = a0; r1[t >> 5] = a1; }
    __syncthreads();
    if (t == 0) {
        float o0 = bd[0], o1 = bd[1];
#pragma unroll
        for (int i = 0; i < 8; i++) { o0 += r0[i]; o1 += r1[i]; }
        out[b * 2]     = o0;
        out[b * 2 + 1] = o1;
    }
}

// ---------------------------------------------------------------------------
// launch
// ---------------------------------------------------------------------------
extern "C" void kernel_launch(void* const* d_in, const int* in_sizes, int n_in,
                              void* d_out, int out_size) {
    const int*   sentence = (const int*)d_in[0];
    const int*   lens     = (const int*)d_in[1];
    const float* emb      = (const float*)d_in[2];
    const float* Wihf     = (const float*)d_in[3];
    const float* Whhf     = (const float*)d_in[4];
    const float* bf       = (const float*)d_in[5];
    const float* Wihb     = (const float*)d_in[6];
    const float* Whhb     = (const float*)d_in[7];
    const float* bb       = (const float*)d_in[8];
    const float* Wd       = (const float*)d_in[9];
    const float* bd       = (const float*)d_in[10];
    float* out = (float*)d_out;

    cudaFuncSetAttribute(proj_kernel, cudaFuncAttributeMaxDynamicSharedMemorySize, PROJ_SMEM);
    cudaFuncSetAttribute(lstm_kernel, cudaFuncAttributeMaxDynamicSharedMemorySize, LSTM_SMEM);

    proj_kernel<<<dim3(Vn / PROJ_VT, 4), 256, PROJ_SMEM>>>(emb, Wihf, bf, Wihb, bb);
    lstm_kernel<<<128, 256, LSTM_SMEM>>>(sentence, lens, Whhf, Whhb);
    dense_kernel<<<Bn, 256>>>(Wd, bd, out);
}

// round 12
// speedup vs baseline: 1.7817x; 1.0068x over previous
#include <cuda_runtime.h>
#include <cstdint>

// Problem constants
#define Tn   2048
#define Bn   64
#define Vn   4096
#define En   128
#define H2n  128
#define Sn   8

// Scratch (no allocations allowed)
__device__ float g_proj[2][Vn * 512];      // proj[d][v][gate] = W_ih_d @ emb[v] + b_d (16 MB, L2-resident)
__device__ float g_pooled[Bn * Sn * 256];  // pooled[b][s][h]  (512 KB)

// ---------------------------------------------------------------------------
// helpers
// ---------------------------------------------------------------------------
__device__ __forceinline__ unsigned long long ffma2(unsigned long long a,
                                                    unsigned long long b,
                                                    unsigned long long c) {
    unsigned long long d;
    asm("fma.rn.f32x2 %0, %1, %2, %3;" : "=l"(d) : "l"(a), "l"(b), "l"(c));
    return d;
}
__device__ __forceinline__ float2 unpack2(unsigned long long u) {
    float2 f;
    f.x = __uint_as_float((unsigned)(u & 0xffffffffull));
    f.y = __uint_as_float((unsigned)(u >> 32));
    return f;
}
__device__ __forceinline__ float tanhf_fast(float x) {
    float y; asm("tanh.approx.f32 %0, %1;" : "=f"(y) : "f"(x)); return y;
}
// sigmoid via MUFU tanh: sig(x) = 0.5*tanh(0.5x) + 0.5
__device__ __forceinline__ float sigm_fast(float x) {
    return fmaf(0.5f, tanhf_fast(0.5f * x), 0.5f);
}
// pack two f32 registers into one 64-bit reg (for fma.rn.f32x2)
__device__ __forceinline__ unsigned long long pk(unsigned lo, unsigned hi) {
    unsigned long long r;
    asm("mov.b64 %0, {%1, %2};" : "=l"(r) : "r"(lo), "r"(hi));
    return r;
}
// round f32 -> bf16 bits (rne), bit-exact manual
__device__ __forceinline__ unsigned f2bf(float x) {
    unsigned u = __float_as_uint(x);
    return (u + 0x7FFFu + ((u >> 16) & 1u)) >> 16;
}

// ---------------------------------------------------------------------------
// Kernel A: proj[d][v][r] = dot(emb[v], W_ih_d[r]) + b_d[r]
// grid (32, 4): y -> (dir, row-half). 256 threads; thread j owns row r = half*256+j,
// ALL 128 row weights in registers (64 f32x2). 128 v per block, 2 v per iter (ILP).
// ---------------------------------------------------------------------------
#define PROJ_VT 128
#define PROJ_SMEM (PROJ_VT * En * 4)   // 65536 B

__global__ void __launch_bounds__(256, 1)
proj_kernel(const float* __restrict__ emb,
            const float* __restrict__ Wf, const float* __restrict__ bf,
            const float* __restrict__ Wb, const float* __restrict__ bb) {
    extern __shared__ float xs[];   // [128 v][128 e]
    int vt   = blockIdx.x * PROJ_VT;
    int d    = blockIdx.y >> 1;
    int half = blockIdx.y & 1;
    int j    = threadIdx.x;
    int r    = half * 256 + j;

    const float* W    = d ? Wb : Wf;
    const float* bias = d ? bb : bf;
    float* outp = g_proj[d];

    // stage x tile: 128 v x 128 floats, coalesced float4
    {
        const float4* src = (const float4*)(emb + vt * En);
        float4* dst = (float4*)xs;
        for (int i = j; i < PROJ_VT * En / 4; i += 256) dst[i] = src[i];
    }

    // row weights fully in regs: 64 f32x2
    unsigned long long wr[64];
    {
        const ulonglong2* pw = (const ulonglong2*)(W + r * En);
#pragma unroll
        for (int q = 0; q < 32; q++) {
            ulonglong2 t = pw[q];
            wr[2 * q] = t.x; wr[2 * q + 1] = t.y;
        }
    }
    float bj = bias[r];
    __syncthreads();

    for (int v = 0; v < PROJ_VT; v += 2) {
        const ulonglong2* xv0 = (const ulonglong2*)(xs + v * En);
        const ulonglong2* xv1 = (const ulonglong2*)(xs + (v + 1) * En);
        unsigned long long a0 = 0, a1 = 0, a2 = 0, a3 = 0;
        unsigned long long b0 = 0, b1 = 0, b2 = 0, b3 = 0;
#pragma unroll
        for (int q = 0; q < 16; q++) {
            ulonglong2 hx0 = xv0[2 * q];
            ulonglong2 hx1 = xv0[2 * q + 1];
            ulonglong2 gx0 = xv1[2 * q];
            ulonglong2 gx1 = xv1[2 * q + 1];
            a0 = ffma2(wr[4 * q],     hx0.x, a0);
            a1 = ffma2(wr[4 * q + 1], hx0.y, a1);
            a2 = ffma2(wr[4 * q + 2], hx1.x, a2);
            a3 = ffma2(wr[4 * q + 3], hx1.y, a3);
            b0 = ffma2(wr[4 * q],     gx0.x, b0);
            b1 = ffma2(wr[4 * q + 1], gx0.y, b1);
            b2 = ffma2(wr[4 * q + 2], gx1.x, b2);
            b3 = ffma2(wr[4 * q + 3], gx1.y, b3);
        }
        float2 f0 = unpack2(a0), f1 = unpack2(a1);
        float2 f2 = unpack2(a2), f3 = unpack2(a3);
        outp[(vt + v) * 512 + r] =
            ((f0.x + f0.y) + (f1.x + f1.y)) + ((f2.x + f2.y) + (f3.x + f3.y)) + bj;
        float2 g0 = unpack2(b0), g1 = unpack2(b1);
        float2 g2 = unpack2(b2), g3 = unpack2(b3);
        outp[(vt + v + 1) * 512 + r] =
            ((g0.x + g0.y) + (g1.x + g1.y)) + ((g2.x + g2.y) + (g3.x + g3.y)) + bj;
    }
}

// ---------------------------------------------------------------------------
// Kernel B: recurrent biLSTM with fused ragged max-pool.
// grid 128 = (sample, direction); 256 threads.
// Pair (2j, 2j+1): thread p owns h-columns [64p, 64p+64) of gate rows
// i_j, f_j, g_j, o_j. One f32x2 accumulator per gate; partials combined via
// 2 shfl_xor; sig(i)*tanh(g) crosses with 1 more shfl. ONE barrier per step.
// All activations via MUFU tanh.approx (sigmoid = 0.5*tanh(0.5x)+0.5).
// Weights: i/f/g halves fp32 in regs (96 f32x2); o half: first 16 cols fp32
// regs, remaining 48 cols streamed from smem as bf16 (halves crossbar traffic;
// o-gate errors don't enter the recurrent cell-state path).
// h double-buffered (removes WAR hazard across the single barrier).
// ---------------------------------------------------------------------------
#define LSTM_SMEM (6 * 256 * 16 + 2 * 136 * 4 + Sn * 128 * 4)   // 29760 B

__global__ void __launch_bounds__(256, 1)
lstm_kernel(const int* __restrict__ sentence, const int* __restrict__ lens,
            const float* __restrict__ Whhf, const float* __restrict__ Whhb) {
    extern __shared__ uint4 dsm4[];
    uint4 (*sWb)[256] = (uint4 (*)[256])dsm4;            // [6][256]: o-row bf16 stream
    float* hA   = (float*)(dsm4 + 6 * 256);              // 136 floats: [0..63],[pad],[64..127],[pad]
    float* hB   = hA + 136;                              // second buffer
    float* wmax = hB + 136;                              // [8][128]

    int bid = blockIdx.x;
    int b = bid >> 1, d = bid & 1;
    int L = lens[b];
    int w = (L + 7) >> 3;          // pooling window (>=128 for L in [1024,2048])
    int k = threadIdx.x;
    int j = k >> 1, p = k & 1;

    const float* W     = d ? Whhb : Whhf;
    const float* projd = g_proj[d];
    const int*   toks  = sentence + b * Tn;

    int rX = p ? (128 + j) : j;          // f : i   (xg row for gX)
    int rY = p ? (384 + j) : (256 + j);  // o : g   (xg row for gY)

    // --- load W_hh halves: i/f/g -> fp32 regs; o: cols [co,co+16) fp32 regs,
    //     cols [co+16,co+64) converted to bf16x2 words in smem ---
    unsigned long long wi[32], wf[32], wg[32], wo[8];
    {
        int co = 64 * p;
        const ulonglong2* pi_ = (const ulonglong2*)(W + j * En + co);
        const ulonglong2* pf_ = (const ulonglong2*)(W + (128 + j) * En + co);
        const ulonglong2* pg_ = (const ulonglong2*)(W + (256 + j) * En + co);
        const ulonglong2* po_ = (const ulonglong2*)(W + (384 + j) * En + co);
#pragma unroll
        for (int q = 0; q < 16; q++) {
            ulonglong2 ti = pi_[q]; wi[2 * q] = ti.x; wi[2 * q + 1] = ti.y;
            ulonglong2 tf = pf_[q]; wf[2 * q] = tf.x; wf[2 * q + 1] = tf.y;
            ulonglong2 tg = pg_[q]; wg[2 * q] = tg.x; wg[2 * q + 1] = tg.y;
        }
#pragma unroll
        for (int q = 0; q < 4; q++) {
            ulonglong2 to = po_[q]; wo[2 * q] = to.x; wo[2 * q + 1] = to.y;
        }
        // bf16 encode: word n holds cols (co+16+2n, co+16+2n+1), n = 0..23
        const float* pof = W + (384 + j) * En + co;
#pragma unroll
        for (int t4 = 0; t4 < 6; t4++) {
            unsigned wd[4];
#pragma unroll
            for (int m = 0; m < 4; m++) {
                int n = t4 * 4 + m;
                unsigned bl = f2bf(pof[16 + 2 * n]);
                unsigned bh = f2bf(pof[16 + 2 * n + 1]);
                wd[m] = (bh << 16) | bl;
            }
            sWb[t4][k] = make_uint4(wd[0], wd[1], wd[2], wd[3]);
        }
    }
    if (k < 136) { hA[k] = 0.f; hB[k] = 0.f; }
    __syncthreads();

    float c = 0.f;
    float rmax = -3.402823e38f;
    int sdir = d ? -1 : 1;
    int seg  = d ? 7 : 0;                  // (L-1)/w == 7 for all valid L
    int cnt  = d ? (L - 7 * w) : w;        // steps until current segment closes
    int hidx = j + ((j >> 6) << 2);        // padded h index for stores
    int poff = p * 68;                     // padded read offset for this half
    int idx  = d ? (L - 1) : 0;            // current time index

    float* hr = hA;   // read buffer (h(t-1))
    float* hw = hB;   // write buffer (h(t))

    // prefetch first xg pair
    int tok0 = toks[idx];
    float xga = __ldg(projd + tok0 * 512 + rX);
    float xgb = __ldg(projd + tok0 * 512 + rY);

    for (int s = 0; s < L; s++) {
        // prefetch next step's xg pair (hides L2 latency under the FMA loop)
        int ni = idx + sdir;
        ni = ni < 0 ? 0 : (ni >= L ? L - 1 : ni);
        int tok2 = __ldg(toks + ni);
        float nxa = __ldg(projd + tok2 * 512 + rX);
        float nxb = __ldg(projd + tok2 * 512 + rY);

        // --- 4 half-row dots against this thread's h half (1 f32x2 acc each) ---
        const ulonglong2* hv = (const ulonglong2*)(hr + poff);
        unsigned long long Pi = 0, Pf = 0, Pg = 0, Po = 0;
        uint4 u4;
#pragma unroll
        for (int q = 0; q < 16; q++) {
            ulonglong2 hp = hv[q];              // 2-addr (even/odd) bank-disjoint LDS.128
            unsigned long long wox, woy;
            if (q < 4) { wox = wo[2 * q]; woy = wo[2 * q + 1]; }
            else {
                int n = q - 4;                  // 0..11
                if ((n & 1) == 0) u4 = sWb[n >> 1][k];   // LDS.128 every other q
                unsigned w01 = (n & 1) ? u4.z : u4.x;
                unsigned w23 = (n & 1) ? u4.w : u4.y;
                wox = pk(w01 << 16, w01 & 0xFFFF0000u);  // bf16 -> f32x2 decode
                woy = pk(w23 << 16, w23 & 0xFFFF0000u);
            }
            Pi = ffma2(wi[2 * q],     hp.x, Pi);
            Pi = ffma2(wi[2 * q + 1], hp.y, Pi);
            Pf = ffma2(wf[2 * q],     hp.x, Pf);
            Pf = ffma2(wf[2 * q + 1], hp.y, Pf);
            Pg = ffma2(wg[2 * q],     hp.x, Pg);
            Pg = ffma2(wg[2 * q + 1], hp.y, Pg);
            Po = ffma2(wox,           hp.x, Po);
            Po = ffma2(woy,           hp.y, Po);
        }
        float2 vi_ = unpack2(Pi); float pi = vi_.x + vi_.y;
        float2 vf_ = unpack2(Pf); float pf = vf_.x + vf_.y;
        float2 vg_ = unpack2(Pg); float pg = vg_.x + vg_.y;
        float2 vo_ = unpack2(Po); float po = vo_.x + vo_.y;

        // combine partials across the pair: even keeps i,g; odd keeps f,o
        float sendA = p ? pi : pf;
        float sendB = p ? pg : po;
        float recvA = __shfl_xor_sync(0xffffffffu, sendA, 1);
        float recvB = __shfl_xor_sync(0xffffffffu, sendB, 1);
        float gX = (p ? pf : pi) + recvA + xga;   // i (even) / f (odd)
        float gY = (p ? po : pg) + recvB + xgb;   // g (even) / o (odd)

        // activations, all on MUFU tanh
        float vX = sigm_fast(gX);                   // sig(i)/sig(f)
        float ty = tanhf_fast(p ? 0.5f * gY : gY);
        float vY = p ? fmaf(0.5f, ty, 0.5f) : ty;   // sig(o)/tanh(g)

        float pvr = __shfl_xor_sync(0xffffffffu, vX * vY, 1);  // sig(i)*tanh(g) -> odd

        c = vX * c + pvr;                           // meaningful on odd lanes
        float hn = vY * tanhf_fast(c);              // sig(o)*tanh(c)
        if (p) hw[hidx] = hn;
        __syncthreads();
        if (p) rmax = fmaxf(rmax, hn);              // off the pre-barrier path

        // segment boundary: flush register max (7-8 crossings per chain)
        if (--cnt == 0) {
            if (p) wmax[seg * 128 + j] = rmax;
            rmax = -3.402823e38f;
            seg += sdir;
            cnt = w;
        }
        idx = ni;
        xga = nxa; xgb = nxb;
        float* t = hr; hr = hw; hw = t;             // swap double buffers
    }
    if (cnt != w && p) wmax[seg * 128 + j] = rmax;   // pending partial segment
    __syncthreads();

    // epilogue: only window 7 can overlap the zero pad (pad length < 8 <= w)
    bool pad7 = (8 * w > L);
    for (int i = k; i < Sn * 128; i += 256) {
        int s = i >> 7, kk = i & 127;
        float v = wmax[i];
        if (s == 7 && pad7) v = fmaxf(v, 0.f);
        g_pooled[(b * Sn + s) * 256 + d * 128 + kk] = v;
    }
}

// ---------------------------------------------------------------------------
// Kernel C: out[b][c] = b_dense[c] + sum_{s,h} pooled[b][s][h] * W_dense[c][h*8+s]
// ---------------------------------------------------------------------------
__global__ void dense_kernel(const float* __restrict__ Wd, const float* __restrict__ bd,
                             float* __restrict__ out) {
    int b = blockIdx.x, t = threadIdx.x;
    const float* p = g_pooled + b * 2048;
    float a0 = 0.f, a1 = 0.f;
    for (int i = t; i < 2048; i += 256) {
        int s = i >> 8, hh = i & 255;
        float v = p[i];
        a0 += v * Wd[hh * 8 + s];
        a1 += v * Wd[2048 + hh * 8 + s];
    }
#pragma unroll
    for (int o = 16; o > 0; o >>= 1) {
        a0 += __shfl_down_sync(0xffffffffu, a0, o);
        a1 += __shfl_down_sync(0xffffffffu, a1, o);
    }
    __shared__ float r0[8], r1[8];
    if ((t & 31) == 0) { r0[t >> 5] = a0; r1[t >> 5] = a1; }
    __syncthreads();
    if (t == 0) {
        float o0 = bd[0], o1 = bd[1];
#pragma unroll
        for (int i = 0; i < 8; i++) { o0 += r0[i]; o1 += r1[i]; }
        out[b * 2]     = o0;
        out[b * 2 + 1] = o1;
    }
}

// ---------------------------------------------------------------------------
// launch
// ---------------------------------------------------------------------------
extern "C" void kernel_launch(void* const* d_in, const int* in_sizes, int n_in,
                              void* d_out, int out_size) {
    const int*   sentence = (const int*)d_in[0];
    const int*   lens     = (const int*)d_in[1];
    const float* emb      = (const float*)d_in[2];
    const float* Wihf     = (const float*)d_in[3];
    const float* Whhf     = (const float*)d_in[4];
    const float* bf       = (const float*)d_in[5];
    const float* Wihb     = (const float*)d_in[6];
    const float* Whhb     = (const float*)d_in[7];
    const float* bb       = (const float*)d_in[8];
    const float* Wd       = (const float*)d_in[9];
    const float* bd       = (const float*)d_in[10];
    float* out = (float*)d_out;

    cudaFuncSetAttribute(proj_kernel, cudaFuncAttributeMaxDynamicSharedMemorySize, PROJ_SMEM);
    cudaFuncSetAttribute(lstm_kernel, cudaFuncAttributeMaxDynamicSharedMemorySize, LSTM_SMEM);

    proj_kernel<<<dim3(Vn / PROJ_VT, 4), 256, PROJ_SMEM>>>(emb, Wihf, bf, Wihb, bb);
    lstm_kernel<<<128, 256, LSTM_SMEM>>>(sentence, lens, Whhf, Whhb);
    dense_kernel<<<Bn, 256>>>(Wd, bd, out);
}

// round 13
// speedup vs baseline: 1.9505x; 1.0948x over previous
#include <cuda_runtime.h>
#include <cuda_fp16.h>
#include <cstdint>

// Problem constants
#define Tn   2048
#define Bn   64
#define Vn   4096
#define En   128
#define H2n  128
#define Sn   8

// Scratch (no allocations allowed)
__device__ float g_proj[2][Vn * 512];      // proj[d][v][gate] = W_ih_d @ emb[v] + b_d (16 MB, L2-resident)
__device__ float g_pooled[Bn * Sn * 256];  // pooled[b][s][h]  (512 KB)

// ---------------------------------------------------------------------------
// helpers
// ---------------------------------------------------------------------------
__device__ __forceinline__ unsigned long long ffma2(unsigned long long a,
                                                    unsigned long long b,
                                                    unsigned long long c) {
    unsigned long long d;
    asm("fma.rn.f32x2 %0, %1, %2, %3;" : "=l"(d) : "l"(a), "l"(b), "l"(c));
    return d;
}
__device__ __forceinline__ float2 unpack2(unsigned long long u) {
    float2 f;
    f.x = __uint_as_float((unsigned)(u & 0xffffffffull));
    f.y = __uint_as_float((unsigned)(u >> 32));
    return f;
}
__device__ __forceinline__ float tanhf_fast(float x) {
    float y; asm("tanh.approx.f32 %0, %1;" : "=f"(y) : "f"(x)); return y;
}
// sigmoid via MUFU tanh: sig(x) = 0.5*tanh(0.5x) + 0.5
__device__ __forceinline__ float sigm_fast(float x) {
    return fmaf(0.5f, tanhf_fast(0.5f * x), 0.5f);
}

// ---------------------------------------------------------------------------
// Kernel A: proj[d][v][r] = dot(emb[v], W_ih_d[r]) + b_d[r]
// grid (32, 4): y -> (dir, row-half). 256 threads; thread j owns row r = half*256+j,
// ALL 128 row weights in registers (64 f32x2). 128 v per block, 2 v per iter (ILP).
// ---------------------------------------------------------------------------
#define PROJ_VT 128
#define PROJ_SMEM (PROJ_VT * En * 4)   // 65536 B

__global__ void __launch_bounds__(256, 1)
proj_kernel(const float* __restrict__ emb,
            const float* __restrict__ Wf, const float* __restrict__ bf,
            const float* __restrict__ Wb, const float* __restrict__ bb) {
    extern __shared__ float xs[];   // [128 v][128 e]
    int vt   = blockIdx.x * PROJ_VT;
    int d    = blockIdx.y >> 1;
    int half = blockIdx.y & 1;
    int j    = threadIdx.x;
    int r    = half * 256 + j;

    const float* W    = d ? Wb : Wf;
    const float* bias = d ? bb : bf;
    float* outp = g_proj[d];

    // stage x tile: 128 v x 128 floats, coalesced float4
    {
        const float4* src = (const float4*)(emb + vt * En);
        float4* dst = (float4*)xs;
        for (int i = j; i < PROJ_VT * En / 4; i += 256) dst[i] = src[i];
    }

    // row weights fully in regs: 64 f32x2
    unsigned long long wr[64];
    {
        const ulonglong2* pw = (const ulonglong2*)(W + r * En);
#pragma unroll
        for (int q = 0; q < 32; q++) {
            ulonglong2 t = pw[q];
            wr[2 * q] = t.x; wr[2 * q + 1] = t.y;
        }
    }
    float bj = bias[r];
    __syncthreads();

    for (int v = 0; v < PROJ_VT; v += 2) {
        const ulonglong2* xv0 = (const ulonglong2*)(xs + v * En);
        const ulonglong2* xv1 = (const ulonglong2*)(xs + (v + 1) * En);
        unsigned long long a0 = 0, a1 = 0, a2 = 0, a3 = 0;
        unsigned long long b0 = 0, b1 = 0, b2 = 0, b3 = 0;
#pragma unroll
        for (int q = 0; q < 16; q++) {
            ulonglong2 hx0 = xv0[2 * q];
            ulonglong2 hx1 = xv0[2 * q + 1];
            ulonglong2 gx0 = xv1[2 * q];
            ulonglong2 gx1 = xv1[2 * q + 1];
            a0 = ffma2(wr[4 * q],     hx0.x, a0);
            a1 = ffma2(wr[4 * q + 1], hx0.y, a1);
            a2 = ffma2(wr[4 * q + 2], hx1.x, a2);
            a3 = ffma2(wr[4 * q + 3], hx1.y, a3);
            b0 = ffma2(wr[4 * q],     gx0.x, b0);
            b1 = ffma2(wr[4 * q + 1], gx0.y, b1);
            b2 = ffma2(wr[4 * q + 2], gx1.x, b2);
            b3 = ffma2(wr[4 * q + 3], gx1.y, b3);
        }
        float2 f0 = unpack2(a0), f1 = unpack2(a1);
        float2 f2 = unpack2(a2), f3 = unpack2(a3);
        outp[(vt + v) * 512 + r] =
            ((f0.x + f0.y) + (f1.x + f1.y)) + ((f2.x + f2.y) + (f3.x + f3.y)) + bj;
        float2 g0 = unpack2(b0), g1 = unpack2(b1);
        float2 g2 = unpack2(b2), g3 = unpack2(b3);
        outp[(vt + v + 1) * 512 + r] =
            ((g0.x + g0.y) + (g1.x + g1.y)) + ((g2.x + g2.y) + (g3.x + g3.y)) + bj;
    }
}

// ---------------------------------------------------------------------------
// Kernel B: recurrent biLSTM with fused ragged max-pool — fp16 HFMA2 dots.
// grid 128 = (sample, direction); 256 threads.
// Pair (2j, 2j+1): thread p owns h-columns [64p, 64p+64) of gate rows
// i_j, f_j, g_j, o_j. W_hh quantized to fp16: ALL 4 gate halves live in
// registers as half2 (128 regs) — ZERO smem weight streaming. h stored as
// half2 (double-buffered, 4-half2 pad between halves for bank-disjoint reads).
// Dots via __hfma2 into 8 half2 accumulators per gate (chain depth 4 bounds
// fp16 rounding); promoted to fp32 at the reduction. HFMA2 rt 2 with 2
// MACs/lane = 2x the fp32 FFMA rate (the R11 roofline). c/activations fp32.
// ---------------------------------------------------------------------------
__global__ void __launch_bounds__(256, 1)
lstm_kernel(const int* __restrict__ sentence, const int* __restrict__ lens,
            const float* __restrict__ Whhf, const float* __restrict__ Whhb) {
    __shared__ uint4 h2raw[2][18];        // 2 x 72 half2: [0..31], pad 4, [36..67]
    __shared__ float wmax[Sn * 128];      // [8][128]

    int bid = blockIdx.x;
    int b = bid >> 1, d = bid & 1;
    int L = lens[b];
    int w = (L + 7) >> 3;          // pooling window (>=128 for L in [1024,2048])
    int k = threadIdx.x;
    int j = k >> 1, p = k & 1;

    const float* W     = d ? Whhb : Whhf;
    const float* projd = g_proj[d];
    const int*   toks  = sentence + b * Tn;

    int rX = p ? (128 + j) : j;          // f : i   (xg row for gX)
    int rY = p ? (384 + j) : (256 + j);  // o : g   (xg row for gY)

    // --- load W_hh halves, quantize to half2 pairs (cols 2m, 2m+1) ---
    __half2 w2i[32], w2f[32], w2g[32], w2o[32];
    {
        int co = 64 * p;
        const float4* pi_ = (const float4*)(W + j * En + co);
        const float4* pf_ = (const float4*)(W + (128 + j) * En + co);
        const float4* pg_ = (const float4*)(W + (256 + j) * En + co);
        const float4* po_ = (const float4*)(W + (384 + j) * En + co);
#pragma unroll
        for (int q = 0; q < 16; q++) {
            float4 vi = pi_[q];
            w2i[2 * q]     = __floats2half2_rn(vi.x, vi.y);
            w2i[2 * q + 1] = __floats2half2_rn(vi.z, vi.w);
            float4 vf = pf_[q];
            w2f[2 * q]     = __floats2half2_rn(vf.x, vf.y);
            w2f[2 * q + 1] = __floats2half2_rn(vf.z, vf.w);
            float4 vg = pg_[q];
            w2g[2 * q]     = __floats2half2_rn(vg.x, vg.y);
            w2g[2 * q + 1] = __floats2half2_rn(vg.z, vg.w);
            float4 vo = po_[q];
            w2o[2 * q]     = __floats2half2_rn(vo.x, vo.y);
            w2o[2 * q + 1] = __floats2half2_rn(vo.z, vo.w);
        }
    }
    // zero both h buffers
    if (k < 36) {
        ((uint*)h2raw[0])[k * 2] = 0; ((uint*)h2raw[0])[k * 2 + 1] = 0;
        ((uint*)h2raw[1])[k * 2] = 0; ((uint*)h2raw[1])[k * 2 + 1] = 0;
    }
    __syncthreads();

    float c = 0.f;
    float rmax = -3.402823e38f;
    int sdir = d ? -1 : 1;
    int seg  = d ? 7 : 0;                  // (L-1)/w == 7 for all valid L
    int cnt  = d ? (L - 7 * w) : w;        // steps until current segment closes
    int idx  = d ? (L - 1) : 0;            // current time index
    // h2 writer: threads with (k&3)==1 own entry m = k>>2 (pairs h_2m, h_2m+1)
    int went  = (k >> 2) + (((k >> 2) >> 5) << 2);   // padded entry index
    bool isw  = (k & 3) == 1;

    int rbuf = 0;

    // prefetch first xg pair
    int tok0 = toks[idx];
    float xga = __ldg(projd + tok0 * 512 + rX);
    float xgb = __ldg(projd + tok0 * 512 + rY);

    for (int s = 0; s < L; s++) {
        // prefetch next step's xg pair (hides L2 latency under the FMA loop)
        int ni = idx + sdir;
        ni = ni < 0 ? 0 : (ni >= L ? L - 1 : ni);
        int tok2 = __ldg(toks + ni);
        float nxa = __ldg(projd + tok2 * 512 + rX);
        float nxb = __ldg(projd + tok2 * 512 + rY);

        // --- load this thread's h half (32 half2) as 8 LDS.128 ---
        uint4 hu[8];
        {
            const uint4* hb = h2raw[rbuf] + p * 9;   // 36 half2 = 9 uint4 offset
#pragma unroll
            for (int i = 0; i < 8; i++) hu[i] = hb[i];
        }
        const __half2* hp = (const __half2*)hu;

        // --- 4 half-row dots, 8 independent half2 accumulator chains each ---
        __half2 ai[8], af[8], ag[8], ao[8];
#pragma unroll
        for (int a = 0; a < 8; a++) {
            ai[a] = __float2half2_rn(0.f); af[a] = __float2half2_rn(0.f);
            ag[a] = __float2half2_rn(0.f); ao[a] = __float2half2_rn(0.f);
        }
#pragma unroll
        for (int m = 0; m < 32; m++) {
            int a = m & 7;
            __half2 h2 = hp[m];
            ai[a] = __hfma2(w2i[m], h2, ai[a]);
            af[a] = __hfma2(w2f[m], h2, af[a]);
            ag[a] = __hfma2(w2g[m], h2, ag[a]);
            ao[a] = __hfma2(w2o[m], h2, ao[a]);
        }
        // reduce: hadd2 tree then promote to fp32
        __half2 si = __hadd2(__hadd2(__hadd2(ai[0], ai[1]), __hadd2(ai[2], ai[3])),
                             __hadd2(__hadd2(ai[4], ai[5]), __hadd2(ai[6], ai[7])));
        __half2 sf = __hadd2(__hadd2(__hadd2(af[0], af[1]), __hadd2(af[2], af[3])),
                             __hadd2(__hadd2(af[4], af[5]), __hadd2(af[6], af[7])));
        __half2 sg = __hadd2(__hadd2(__hadd2(ag[0], ag[1]), __hadd2(ag[2], ag[3])),
                             __hadd2(__hadd2(ag[4], ag[5]), __hadd2(ag[6], ag[7])));
        __half2 so = __hadd2(__hadd2(__hadd2(ao[0], ao[1]), __hadd2(ao[2], ao[3])),
                             __hadd2(__hadd2(ao[4], ao[5]), __hadd2(ao[6], ao[7])));
        float pi = __low2float(si) + __high2float(si);
        float pf = __low2float(sf) + __high2float(sf);
        float pg = __low2float(sg) + __high2float(sg);
        float po = __low2float(so) + __high2float(so);

        // combine partials across the pair: even keeps i,g; odd keeps f,o
        float sendA = p ? pi : pf;
        float sendB = p ? pg : po;
        float recvA = __shfl_xor_sync(0xffffffffu, sendA, 1);
        float recvB = __shfl_xor_sync(0xffffffffu, sendB, 1);
        float gX = (p ? pf : pi) + recvA + xga;   // i (even) / f (odd)
        float gY = (p ? po : pg) + recvB + xgb;   // g (even) / o (odd)

        // activations on MUFU tanh
        float vX = sigm_fast(gX);                   // sig(i)/sig(f)
        float ty = tanhf_fast(p ? 0.5f * gY : gY);
        float vY = p ? fmaf(0.5f, ty, 0.5f) : ty;   // sig(o)/tanh(g)

        float pvr = __shfl_xor_sync(0xffffffffu, vX * vY, 1);  // sig(i)*tanh(g) -> odd

        c = vX * c + pvr;                           // meaningful on odd lanes
        float hn = vY * tanhf_fast(c);              // sig(o)*tanh(c)

        // pack h pair (h_2m, h_2m+1) from odd lanes 4m+1 / 4m+3, store half2
        float hpart = __shfl_xor_sync(0xffffffffu, hn, 2);
        if (isw) {
            ((__half2*)h2raw[rbuf ^ 1])[went] = __floats2half2_rn(hn, hpart);
        }
        __syncthreads();
        if (p) rmax = fmaxf(rmax, hn);

        // segment boundary: flush register max (7-8 crossings per chain)
        if (--cnt == 0) {
            if (p) wmax[seg * 128 + j] = rmax;
            rmax = -3.402823e38f;
            seg += sdir;
            cnt = w;
        }
        idx = ni;
        xga = nxa; xgb = nxb;
        rbuf ^= 1;                                  // swap double buffers
    }
    if (cnt != w && p) wmax[seg * 128 + j] = rmax;   // pending partial segment
    __syncthreads();

    // epilogue: only window 7 can overlap the zero pad (pad length < 8 <= w)
    bool pad7 = (8 * w > L);
    for (int i = k; i < Sn * 128; i += 256) {
        int s = i >> 7, kk = i & 127;
        float v = wmax[i];
        if (s == 7 && pad7) v = fmaxf(v, 0.f);
        g_pooled[(b * Sn + s) * 256 + d * 128 + kk] = v;
    }
}

// ---------------------------------------------------------------------------
// Kernel C: out[b][c] = b_dense[c] + sum_{s,h} pooled[b][s][h] * W_dense[c][h*8+s]
// ---------------------------------------------------------------------------
__global__ void dense_kernel(const float* __restrict__ Wd, const float* __restrict__ bd,
                             float* __restrict__ out) {
    int b = blockIdx.x, t = threadIdx.x;
    const float* p = g_pooled + b * 2048;
    float a0 = 0.f, a1 = 0.f;
    for (int i = t; i < 2048; i += 256) {
        int s = i >> 8, hh = i & 255;
        float v = p[i];
        a0 += v * Wd[hh * 8 + s];
        a1 += v * Wd[2048 + hh * 8 + s];
    }
#pragma unroll
    for (int o = 16; o > 0; o >>= 1) {
        a0 += __shfl_down_sync(0xffffffffu, a0, o);
        a1 += __shfl_down_sync(0xffffffffu, a1, o);
    }
    __shared__ float r0[8], r1[8];
    if ((t & 31) == 0) { r0[t >> 5] = a0; r1[t >> 5] = a1; }
    __syncthreads();
    if (t == 0) {
        float o0 = bd[0], o1 = bd[1];
#pragma unroll
        for (int i = 0; i < 8; i++) { o0 += r0[i]; o1 += r1[i]; }
        out[b * 2]     = o0;
        out[b * 2 + 1] = o1;
    }
}

// ---------------------------------------------------------------------------
// launch
// ---------------------------------------------------------------------------
extern "C" void kernel_launch(void* const* d_in, const int* in_sizes, int n_in,
                              void* d_out, int out_size) {
    const int*   sentence = (const int*)d_in[0];
    const int*   lens     = (const int*)d_in[1];
    const float* emb      = (const float*)d_in[2];
    const float* Wihf     = (const float*)d_in[3];
    const float* Whhf     = (const float*)d_in[4];
    const float* bf       = (const float*)d_in[5];
    const float* Wihb     = (const float*)d_in[6];
    const float* Whhb     = (const float*)d_in[7];
    const float* bb       = (const float*)d_in[8];
    const float* Wd       = (const float*)d_in[9];
    const float* bd       = (const float*)d_in[10];
    float* out = (float*)d_out;

    cudaFuncSetAttribute(proj_kernel, cudaFuncAttributeMaxDynamicSharedMemorySize, PROJ_SMEM);

    proj_kernel<<<dim3(Vn / PROJ_VT, 4), 256, PROJ_SMEM>>>(emb, Wihf, bf, Wihb, bb);
    lstm_kernel<<<128, 256>>>(sentence, lens, Whhf, Whhb);
    dense_kernel<<<Bn, 256>>>(Wd, bd, out);
}